// round 10
// baseline (speedup 1.0000x reference)
#include <cuda_runtime.h>
#include <math.h>
#include <stdint.h>

#define B_  2
#define S_  2048
#define D_  1024
#define H_  16
#define DK_ 64
#define M_  (B_*S_)

// k-group permutation: within each 8-wide k group, position 2i holds logical
// col i, position 2i+1 holds logical col i+4. Applied identically to BOTH mma
// operands -> bit-exact results, fragment loads become single LDS.64.
#define PERM8(j) (((j) < 4) ? 2*(j) : 2*(j) - 7)

// ---------------------------------------------------------------------------
// Scratch (__device__ globals; allocation-free contract)
// ---------------------------------------------------------------------------
__device__ __align__(16) float g_Xt [M_*D_];            // X tf32, k-permuted
__device__ __align__(16) float g_Wt [4*(size_t)D_*D_];  // weights tf32, k-permuted
__device__ __align__(16) float g_AOt[M_*D_];            // attn out tf32, k-permuted
__device__ __align__(16) float g_Q[B_*H_*S_*DK_];       // [B,H,S,DK] dk-permuted, *log2(e)/8
__device__ __align__(16) float g_K[B_*H_*S_*DK_];       // [B,H,S,DK] dk-permuted
__device__ __align__(16) float g_V[B_*H_*S_*DK_];       // [B,H,DK,S] s-permuted

// ---------------------------------------------------------------------------
// PTX wrappers
// ---------------------------------------------------------------------------
__device__ __forceinline__ uint32_t smem_u32(const void* p) {
    uint32_t a;
    asm("{ .reg .u64 t; cvta.to.shared.u64 t, %1; cvt.u32.u64 %0, t; }"
        : "=r"(a) : "l"(p));
    return a;
}
__device__ __forceinline__ void cp16(uint32_t dst, const void* src) {
    asm volatile("cp.async.cg.shared.global [%0], [%1], 16;"
                 :: "r"(dst), "l"(src));
}
#define CP_COMMIT() asm volatile("cp.async.commit_group;")
#define CP_WAIT1()  asm volatile("cp.async.wait_group 1;")

__device__ __forceinline__ void mma_tf32(float (&d)[4], const uint32_t (&a)[4],
                                         uint32_t b0, uint32_t b1) {
    asm volatile(
        "mma.sync.aligned.m16n8k8.row.col.f32.tf32.tf32.f32 "
        "{%0,%1,%2,%3}, {%4,%5,%6,%7}, {%8,%9}, {%0,%1,%2,%3};"
        : "+f"(d[0]), "+f"(d[1]), "+f"(d[2]), "+f"(d[3])
        : "r"(a[0]), "r"(a[1]), "r"(a[2]), "r"(a[3]), "r"(b0), "r"(b1));
}
__device__ __forceinline__ float ex2f(float x) {
    float y; asm("ex2.approx.f32 %0, %1;" : "=f"(y) : "f"(x)); return y;
}
__device__ __forceinline__ float tf32r(float x) {
    uint32_t r; asm("cvt.rna.tf32.f32 %0, %1;" : "=r"(r) : "f"(x));
    return __uint_as_float(r);
}

#define SC_Q 0.18033688011112042f   // log2(e)/8, folded into Q

// ---------------------------------------------------------------------------
// Prep: tf32-round (rna; mma truncates raw fp32) + k-group permute.
// ---------------------------------------------------------------------------
__device__ __forceinline__ void conv8(const float* src, float* dst, size_t i) {
    float4 v = *(const float4*)(src + i);
    float4 w = *(const float4*)(src + i + 4);
    *(float2*)(dst + i)     = make_float2(tf32r(v.x), tf32r(w.x));
    *(float2*)(dst + i + 2) = make_float2(tf32r(v.y), tf32r(w.y));
    *(float2*)(dst + i + 4) = make_float2(tf32r(v.z), tf32r(w.z));
    *(float2*)(dst + i + 6) = make_float2(tf32r(v.w), tf32r(w.w));
}
__global__ __launch_bounds__(256)
void conv_x(const float* __restrict__ src, float* __restrict__ dst)
{
    size_t i = ((size_t)blockIdx.x * blockDim.x + threadIdx.x) * 8;
    conv8(src, dst, i);
}
__global__ __launch_bounds__(256)
void conv_w4(const float* __restrict__ w0, const float* __restrict__ w1,
             const float* __restrict__ w2, const float* __restrict__ w3,
             float* __restrict__ dst)
{
    const float* srcs[4] = {w0, w1, w2, w3};
    const float* src = srcs[blockIdx.y];
    float* d = dst + (size_t)blockIdx.y * D_ * D_;
    size_t i = ((size_t)blockIdx.x * blockDim.x + threadIdx.x) * 8;
    conv8(src, d, i);
}

// ---------------------------------------------------------------------------
// tf32 GEMM: CTA 128x128, 8 warps of 32x64 (mt=2, nt=8), BK=32, 2-stage.
// Per k8 step: 12 LDS.64 : 16 mma.
// DEST: 0 = Cout fp32 [M,D]; 1 = g_Q (+RoPE,*SC_Q); 2 = g_K (+RoPE);
//       3 = g_V transposed [B,H,DK,S] s-permuted
// ---------------------------------------------------------------------------
#define BM 128
#define BN 128
#define BK 32
#define NIT (D_/BK)
#define TROW 40
#define TSB_OFF (BM*TROW)
#define TSTG ((BM*TROW + BN*TROW)*4)    // 40960 bytes
#define TSMEM (2*TSTG)                  // 81920 -> 2 CTA/SM

template<int DEST>
__global__ __launch_bounds__(256, 2)
void gemm_tf32(const float* __restrict__ A, const float* __restrict__ W,
               float* __restrict__ Cout, const int* __restrict__ tokpos)
{
    extern __shared__ __align__(16) char smem[];
    const int tid  = threadIdx.x;
    const int lane = tid & 31, w = tid >> 5;
    const int wm = (w & 3) * 32;
    const int wn = (w >> 2) * 64;
    const int m0 = blockIdx.x * BM;
    const int n0 = blockIdx.y * BN;
    const int rg = lane >> 2, tc = lane & 3;

    auto load_stage = [&](int st, int it) {
        float* s = (float*)(smem + st * TSTG);
        const int kk = it * BK;
#pragma unroll
        for (int i = 0; i < 4; i++) {           // A: 128 rows x 8 chunks
            int idx = tid + i * 256;
            int row = idx >> 3, ch = idx & 7;
            cp16(smem_u32(s + row * TROW + ch * 4),
                 A + (size_t)(m0 + row) * D_ + kk + ch * 4);
        }
        float* sB = s + TSB_OFF;
#pragma unroll
        for (int i = 0; i < 4; i++) {           // B: 128 rows x 8 chunks
            int idx = tid + i * 256;
            int row = idx >> 3, ch = idx & 7;
            cp16(smem_u32(sB + row * TROW + ch * 4),
                 W + (size_t)(n0 + row) * D_ + kk + ch * 4);
        }
    };

    float acc[2][8][4];
#pragma unroll
    for (int mt = 0; mt < 2; mt++)
#pragma unroll
        for (int nt = 0; nt < 8; nt++)
#pragma unroll
            for (int r = 0; r < 4; r++) acc[mt][nt][r] = 0.f;

    load_stage(0, 0); CP_COMMIT();
    load_stage(1, 1); CP_COMMIT();

    for (int it = 0; it < NIT; it++) {
        CP_WAIT1();
        __syncthreads();

        const float* s  = (const float*)(smem + (it & 1) * TSTG);
        const float* sB = s + TSB_OFF;
#pragma unroll
        for (int ks = 0; ks < 4; ks++) {
            uint32_t a[2][4];
#pragma unroll
            for (int mt = 0; mt < 2; mt++) {
                const float* base = s + (wm + mt * 16 + rg) * TROW + ks * 8 + 2 * tc;
                uint2 r1 = *(const uint2*)(base);
                uint2 r2 = *(const uint2*)(base + 8 * TROW);
                a[mt][0] = r1.x; a[mt][1] = r2.x; a[mt][2] = r1.y; a[mt][3] = r2.y;
            }
#pragma unroll
            for (int nt = 0; nt < 8; nt++) {
                uint2 bb = *(const uint2*)(sB + (wn + nt * 8 + rg) * TROW + ks * 8 + 2 * tc);
#pragma unroll
                for (int mt = 0; mt < 2; mt++)
                    mma_tf32(acc[mt][nt], a[mt], bb.x, bb.y);
            }
        }
        __syncthreads();
        if (it + 2 < NIT) load_stage(it & 1, it + 2);
        CP_COMMIT();
    }

#pragma unroll
    for (int mt = 0; mt < 2; mt++) {
        const int r0 = m0 + wm + mt * 16 + (lane >> 2);
#pragma unroll
        for (int nt = 0; nt < 8; nt++) {
            const int ncol = n0 + wn + nt * 8 + (lane & 3) * 2;   // even
            if (DEST == 0) {
                *(float2*)(Cout + (size_t)r0 * D_ + ncol) =
                    make_float2(acc[mt][nt][0], acc[mt][nt][1]);
                *(float2*)(Cout + (size_t)(r0 + 8) * D_ + ncol) =
                    make_float2(acc[mt][nt][2], acc[mt][nt][3]);
            } else if (DEST == 3) {
                const int h = ncol >> 6, dk = ncol & 63;
#pragma unroll
                for (int rr = 0; rr < 2; rr++) {
                    const int m = r0 + rr * 8;
                    const int bb = m >> 11, ss = m & (S_ - 1);
                    const int sp = (ss & ~7) + PERM8(ss & 7);
                    size_t base = ((size_t)(bb * H_ + h)) * DK_ * S_;
                    g_V[base + (size_t)dk * S_ + sp]       = tf32r(acc[mt][nt][2 * rr]);
                    g_V[base + (size_t)(dk + 1) * S_ + sp] = tf32r(acc[mt][nt][2 * rr + 1]);
                }
            } else {
                float* Dst = (DEST == 1) ? g_Q : g_K;
                const int h = ncol >> 6, dk = ncol & 63;
                const int dg = dk & ~7, dl = dk & 7;
                const int p0 = dg + PERM8(dl);
                const int p1 = dg + PERM8(dl + 1);
                const float fr = powf(10000.f, -(float)dk / 64.f);
#pragma unroll
                for (int rr = 0; rr < 2; rr++) {
                    const int m = r0 + rr * 8;
                    const int bb = m >> 11, ss = m & (S_ - 1);
                    const float pos = (float)tokpos[ss];
                    float sn, cs;
                    sincosf(pos * fr, &sn, &cs);
                    float e  = acc[mt][nt][2 * rr];
                    float od = acc[mt][nt][2 * rr + 1];
                    float v0 = e * cs - od * sn;
                    float v1 = e * sn + od * cs;
                    if (DEST == 1) { v0 *= SC_Q; v1 *= SC_Q; }
                    size_t ib = (((size_t)(bb * H_ + h)) * S_ + ss) * DK_;
                    Dst[ib + p0] = tf32r(v0);
                    Dst[ib + p1] = tf32r(v1);
                }
            }
        }
    }
}

// ---------------------------------------------------------------------------
// Flash attention, single-pass tf32. CTA = 256q x 64kv, 8 warps of 32q.
// Q pre-scaled; V pre-transposed+s-permuted. 1 CTA/SM, 256 threads.
// smem: Q 256 rows | KV 2 stages x (64 K rows + 64 V rows) | P 8 x 32 rows
// ---------------------------------------------------------------------------
#define AQ  256
#define AST 72
#define OKV0 (AQ*AST)                        // 18432 floats
#define OP   (OKV0 + 2*128*AST)              // 36864
#define ATT_FLOATS (OP + 8*32*AST)           // 55296
#define ATT_SMEM (ATT_FLOATS*4)              // 221184 -> 1 CTA/SM

__global__ __launch_bounds__(256, 1)
void attn_tf32()
{
    extern __shared__ __align__(16) float sm[];
    const int tid = threadIdx.x;
    const int lane = tid & 31, w = tid >> 5;
    const int rg = lane >> 2, tc = lane & 3;
    const int qt = (int)(gridDim.x - 1 - blockIdx.x);  // long rows first
    const int h  = blockIdx.y, b = blockIdx.z;
    const int q0 = qt * AQ;
    const int ktmax = 4 * qt + 3;
    const size_t gqk = ((size_t)(b * H_ + h)) * S_ * DK_;
    const size_t gvt = ((size_t)(b * H_ + h)) * DK_ * S_;

    // Q tile: 256 rows x 16 chunks
#pragma unroll
    for (int i = 0; i < 16; i++) {
        int idx = tid + i * 256;
        int r = idx >> 4, ch = idx & 15;
        cp16(smem_u32(sm + r * AST + ch * 4),
             g_Q + gqk + (size_t)(q0 + r) * DK_ + ch * 4);
    }
    auto load_kv = [&](int st, int kt) {
        float* sK = sm + OKV0 + st * (128 * AST);
        float* sV = sK + 64 * AST;
#pragma unroll
        for (int i = 0; i < 4; i++) {
            int idx = tid + i * 256;
            int r = idx >> 4, ch = idx & 15;
            cp16(smem_u32(sK + r * AST + ch * 4),
                 g_K + gqk + (size_t)(kt * 64 + r) * DK_ + ch * 4);
            cp16(smem_u32(sV + r * AST + ch * 4),
                 g_V + gvt + (size_t)r * S_ + kt * 64 + ch * 4);
        }
    };
    load_kv(0, 0); CP_COMMIT();
    load_kv(1, 1); CP_COMMIT();

    float o[2][8][4];
#pragma unroll
    for (int mt = 0; mt < 2; mt++)
#pragma unroll
        for (int d = 0; d < 8; d++)
#pragma unroll
            for (int r = 0; r < 4; r++) o[mt][d][r] = 0.f;
    float mi[2][2], li[2][2];
#pragma unroll
    for (int mt = 0; mt < 2; mt++) {
        mi[mt][0] = -1e30f; mi[mt][1] = -1e30f;
        li[mt][0] = 0.f;    li[mt][1] = 0.f;
    }
    const int colx = 2 * tc;
    const int pp0 = PERM8(colx);
    const int pp1 = PERM8(colx + 1);
    float* pwf = sm + OP + w * 32 * AST;
    const float* qbase = sm + (w * 32 + rg) * AST + 2 * tc;  // rows <= 255: in Q region

    CP_WAIT1();
    __syncthreads();

    for (int kt = 0; kt <= ktmax; kt++) {
        if (kt) { CP_WAIT1(); __syncthreads(); }
        const float* sK = sm + OKV0 + (kt & 1) * (128 * AST);
        const float* sV = sK + 64 * AST;

        // ---- S = Q K^T ----
        float s[2][8][4];
#pragma unroll
        for (int mt = 0; mt < 2; mt++)
#pragma unroll
            for (int nt = 0; nt < 8; nt++)
#pragma unroll
                for (int r = 0; r < 4; r++) s[mt][nt][r] = 0.f;
#pragma unroll
        for (int ks = 0; ks < 8; ks++) {
            uint32_t qa[2][4];
#pragma unroll
            for (int mt = 0; mt < 2; mt++) {
                const float* qb = qbase + mt * 16 * AST + ks * 8;
                uint2 r1 = *(const uint2*)(qb);
                uint2 r2 = *(const uint2*)(qb + 8 * AST);
                qa[mt][0] = r1.x; qa[mt][1] = r2.x; qa[mt][2] = r1.y; qa[mt][3] = r2.y;
            }
#pragma unroll
            for (int nt = 0; nt < 8; nt++) {
                uint2 kb = *(const uint2*)(sK + (nt * 8 + rg) * AST + ks * 8 + 2 * tc);
#pragma unroll
                for (int mt = 0; mt < 2; mt++)
                    mma_tf32(s[mt][nt], qa[mt], kb.x, kb.y);
            }
        }

        // ---- causal mask (tiles at/after the diagonal band) ----
        if (kt >= 4 * qt) {
            const int dq = (kt - 4 * qt) * 64;   // k0 - q0
#pragma unroll
            for (int mt = 0; mt < 2; mt++) {
                const int wrow = w * 32 + mt * 16 + rg;
#pragma unroll
                for (int nt = 0; nt < 8; nt++) {
                    const int c = nt * 8 + colx + dq;
                    if (c     > wrow)     s[mt][nt][0] = -1e30f;
                    if (c + 1 > wrow)     s[mt][nt][1] = -1e30f;
                    if (c     > wrow + 8) s[mt][nt][2] = -1e30f;
                    if (c + 1 > wrow + 8) s[mt][nt][3] = -1e30f;
                }
            }
        }

        // ---- online softmax (base-2, scale pre-folded) ----
#pragma unroll
        for (int mt = 0; mt < 2; mt++) {
            float r0 = -1e30f, r1 = -1e30f;
#pragma unroll
            for (int nt = 0; nt < 8; nt++) {
                r0 = fmaxf(r0, fmaxf(s[mt][nt][0], s[mt][nt][1]));
                r1 = fmaxf(r1, fmaxf(s[mt][nt][2], s[mt][nt][3]));
            }
            r0 = fmaxf(r0, __shfl_xor_sync(0xffffffffu, r0, 1));
            r0 = fmaxf(r0, __shfl_xor_sync(0xffffffffu, r0, 2));
            r1 = fmaxf(r1, __shfl_xor_sync(0xffffffffu, r1, 1));
            r1 = fmaxf(r1, __shfl_xor_sync(0xffffffffu, r1, 2));
            const float mn0 = fmaxf(mi[mt][0], r0), mn1 = fmaxf(mi[mt][1], r1);
            const float c0 = ex2f(mi[mt][0] - mn0), c1 = ex2f(mi[mt][1] - mn1);
            float sum0 = 0.f, sum1 = 0.f;
#pragma unroll
            for (int nt = 0; nt < 8; nt++) {
                s[mt][nt][0] = ex2f(s[mt][nt][0] - mn0);
                s[mt][nt][1] = ex2f(s[mt][nt][1] - mn0);
                s[mt][nt][2] = ex2f(s[mt][nt][2] - mn1);
                s[mt][nt][3] = ex2f(s[mt][nt][3] - mn1);
                sum0 += s[mt][nt][0] + s[mt][nt][1];
                sum1 += s[mt][nt][2] + s[mt][nt][3];
            }
            sum0 += __shfl_xor_sync(0xffffffffu, sum0, 1);
            sum0 += __shfl_xor_sync(0xffffffffu, sum0, 2);
            sum1 += __shfl_xor_sync(0xffffffffu, sum1, 1);
            sum1 += __shfl_xor_sync(0xffffffffu, sum1, 2);
            li[mt][0] = li[mt][0] * c0 + sum0;
            li[mt][1] = li[mt][1] * c1 + sum1;
            mi[mt][0] = mn0; mi[mt][1] = mn1;
#pragma unroll
            for (int d = 0; d < 8; d++) {
                o[mt][d][0] *= c0; o[mt][d][1] *= c0;
                o[mt][d][2] *= c1; o[mt][d][3] *= c1;
            }

            // stage P (tf32, s-permuted) in per-warp smem
            float* pr0 = pwf + (mt * 16 + rg) * AST;
            float* pr1 = pwf + (mt * 16 + rg + 8) * AST;
#pragma unroll
            for (int nt = 0; nt < 8; nt++) {
                pr0[nt * 8 + pp0] = tf32r(s[mt][nt][0]);
                pr0[nt * 8 + pp1] = tf32r(s[mt][nt][1]);
                pr1[nt * 8 + pp0] = tf32r(s[mt][nt][2]);
                pr1[nt * 8 + pp1] = tf32r(s[mt][nt][3]);
            }
        }
        __syncwarp();

        // ---- O += P V ----
#pragma unroll
        for (int ks = 0; ks < 8; ks++) {
            uint32_t pa[2][4];
#pragma unroll
            for (int mt = 0; mt < 2; mt++) {
                const float* pb = pwf + (mt * 16 + rg) * AST + ks * 8 + 2 * tc;
                uint2 r1v = *(const uint2*)(pb);
                uint2 r2v = *(const uint2*)(pb + 8 * AST);
                pa[mt][0] = r1v.x; pa[mt][1] = r2v.x; pa[mt][2] = r1v.y; pa[mt][3] = r2v.y;
            }
#pragma unroll
            for (int nt = 0; nt < 8; nt++) {
                uint2 vb = *(const uint2*)(sV + (nt * 8 + rg) * AST + ks * 8 + 2 * tc);
#pragma unroll
                for (int mt = 0; mt < 2; mt++)
                    mma_tf32(o[mt][nt], pa[mt], vb.x, vb.y);
            }
        }

        __syncthreads();
        if (kt + 2 <= ktmax) load_kv(kt & 1, kt + 2);
        CP_COMMIT();
    }

    // ---- epilogue: normalize, write tf32 k-permuted [B,S,H*DK] ----
    const int op0 = PERM8(colx);
    const int op1 = PERM8(colx + 1);
#pragma unroll
    for (int mt = 0; mt < 2; mt++) {
        const float inv0 = 1.f / li[mt][0], inv1 = 1.f / li[mt][1];
        const int grow0 = q0 + w * 32 + mt * 16 + rg;
#pragma unroll
        for (int d = 0; d < 8; d++) {
            const int cb = h * 64 + d * 8;
            float* a0 = g_AOt + ((size_t)b * S_ + grow0) * D_ + cb;
            float* a1 = g_AOt + ((size_t)b * S_ + grow0 + 8) * D_ + cb;
            a0[op0] = tf32r(o[mt][d][0] * inv0); a0[op1] = tf32r(o[mt][d][1] * inv0);
            a1[op0] = tf32r(o[mt][d][2] * inv1); a1[op1] = tf32r(o[mt][d][3] * inv1);
        }
    }
}

// ---------------------------------------------------------------------------
// Host
// ---------------------------------------------------------------------------
extern "C" void kernel_launch(void* const* d_in, const int* in_sizes, int n_in,
                              void* d_out, int out_size)
{
    const float* x  = (const float*)d_in[0];
    const float* qw = (const float*)d_in[1];
    const float* kw = (const float*)d_in[2];
    const float* vw = (const float*)d_in[3];
    const float* ow = (const float*)d_in[4];
    const int*   tp = (const int*)d_in[6];
    float* out = (float*)d_out;

    void *xt, *wt, *aot;
    cudaGetSymbolAddress(&xt,  g_Xt);
    cudaGetSymbolAddress(&wt,  g_Wt);
    cudaGetSymbolAddress(&aot, g_AOt);
    float* Xt  = (float*)xt;
    float* Wt  = (float*)wt;
    float* AOt = (float*)aot;

    conv_x<<<M_*D_/8/256, 256>>>(x, Xt);
    dim3 wgrid(D_*D_/8/256, 4);
    conv_w4<<<wgrid, 256>>>(qw, kw, vw, ow, Wt);

    cudaFuncSetAttribute(gemm_tf32<0>, cudaFuncAttributeMaxDynamicSharedMemorySize, TSMEM);
    cudaFuncSetAttribute(gemm_tf32<1>, cudaFuncAttributeMaxDynamicSharedMemorySize, TSMEM);
    cudaFuncSetAttribute(gemm_tf32<2>, cudaFuncAttributeMaxDynamicSharedMemorySize, TSMEM);
    cudaFuncSetAttribute(gemm_tf32<3>, cudaFuncAttributeMaxDynamicSharedMemorySize, TSMEM);
    cudaFuncSetAttribute(attn_tf32, cudaFuncAttributeMaxDynamicSharedMemorySize, ATT_SMEM);

    dim3 ggrid(M_ / BM, D_ / BN);   // (32, 8)
    gemm_tf32<1><<<ggrid, 256, TSMEM>>>(Xt, Wt,                   nullptr, tp);
    gemm_tf32<2><<<ggrid, 256, TSMEM>>>(Xt, Wt + 1*(size_t)D_*D_, nullptr, tp);
    gemm_tf32<3><<<ggrid, 256, TSMEM>>>(Xt, Wt + 2*(size_t)D_*D_, nullptr, tp);

    dim3 agrid(S_ / AQ, H_, B_);    // (8, 16, 2)
    attn_tf32<<<agrid, 256, ATT_SMEM>>>();

    gemm_tf32<0><<<ggrid, 256, TSMEM>>>(AOt, Wt + 3*(size_t)D_*D_, out, tp);
}

// round 11
// speedup vs baseline: 1.1472x; 1.1472x over previous
#include <cuda_runtime.h>
#include <math.h>
#include <stdint.h>

#define B_  2
#define S_  2048
#define D_  1024
#define H_  16
#define DK_ 64
#define M_  (B_*S_)

// k-group permutation: within each 8-wide k group, position 2i holds logical
// col i, position 2i+1 holds logical col i+4. Applied identically to BOTH mma
// operands -> bit-exact results, fragment loads become single LDS.64.
#define PERM8(j) (((j) < 4) ? 2*(j) : 2*(j) - 7)

// ---------------------------------------------------------------------------
// Scratch (__device__ globals; allocation-free contract)
// ---------------------------------------------------------------------------
__device__ __align__(16) float g_Xt [M_*D_];            // X tf32, k-permuted
__device__ __align__(16) float g_Wt [4*(size_t)D_*D_];  // weights tf32, k-permuted
__device__ __align__(16) float g_AOt[M_*D_];            // attn out tf32, k-permuted
__device__ __align__(16) float g_Q[B_*H_*S_*DK_];       // [B,H,S,DK] dk-permuted, *log2(e)/8
__device__ __align__(16) float g_K[B_*H_*S_*DK_];       // [B,H,S,DK] dk-permuted
__device__ __align__(16) float g_V[B_*H_*S_*DK_];       // [B,H,DK,S] s-permuted

// ---------------------------------------------------------------------------
// PTX wrappers
// ---------------------------------------------------------------------------
__device__ __forceinline__ uint32_t smem_u32(const void* p) {
    uint32_t a;
    asm("{ .reg .u64 t; cvta.to.shared.u64 t, %1; cvt.u32.u64 %0, t; }"
        : "=r"(a) : "l"(p));
    return a;
}
__device__ __forceinline__ void cp16(uint32_t dst, const void* src) {
    asm volatile("cp.async.cg.shared.global [%0], [%1], 16;"
                 :: "r"(dst), "l"(src));
}
#define CP_COMMIT() asm volatile("cp.async.commit_group;")
#define CP_WAIT1()  asm volatile("cp.async.wait_group 1;")

__device__ __forceinline__ void mma_tf32(float (&d)[4], const uint32_t (&a)[4],
                                         uint32_t b0, uint32_t b1) {
    asm volatile(
        "mma.sync.aligned.m16n8k8.row.col.f32.tf32.tf32.f32 "
        "{%0,%1,%2,%3}, {%4,%5,%6,%7}, {%8,%9}, {%0,%1,%2,%3};"
        : "+f"(d[0]), "+f"(d[1]), "+f"(d[2]), "+f"(d[3])
        : "r"(a[0]), "r"(a[1]), "r"(a[2]), "r"(a[3]), "r"(b0), "r"(b1));
}
__device__ __forceinline__ float ex2f(float x) {
    float y; asm("ex2.approx.f32 %0, %1;" : "=f"(y) : "f"(x)); return y;
}
__device__ __forceinline__ float tf32r(float x) {
    uint32_t r; asm("cvt.rna.tf32.f32 %0, %1;" : "=r"(r) : "f"(x));
    return __uint_as_float(r);
}

#define SC_Q 0.18033688011112042f   // log2(e)/8, folded into Q at projection

// ---------------------------------------------------------------------------
// Prep: tf32-round (rna; mma truncates raw fp32) + k-group permute.
// ---------------------------------------------------------------------------
__device__ __forceinline__ void conv8(const float* src, float* dst, size_t i) {
    float4 v = *(const float4*)(src + i);
    float4 w = *(const float4*)(src + i + 4);
    *(float2*)(dst + i)     = make_float2(tf32r(v.x), tf32r(w.x));
    *(float2*)(dst + i + 2) = make_float2(tf32r(v.y), tf32r(w.y));
    *(float2*)(dst + i + 4) = make_float2(tf32r(v.z), tf32r(w.z));
    *(float2*)(dst + i + 6) = make_float2(tf32r(v.w), tf32r(w.w));
}
__global__ __launch_bounds__(256)
void conv_x(const float* __restrict__ src, float* __restrict__ dst)
{
    size_t i = ((size_t)blockIdx.x * blockDim.x + threadIdx.x) * 8;
    conv8(src, dst, i);
}
__global__ __launch_bounds__(256)
void conv_w4(const float* __restrict__ w0, const float* __restrict__ w1,
             const float* __restrict__ w2, const float* __restrict__ w3,
             float* __restrict__ dst)
{
    const float* srcs[4] = {w0, w1, w2, w3};
    const float* src = srcs[blockIdx.y];
    float* d = dst + (size_t)blockIdx.y * D_ * D_;
    size_t i = ((size_t)blockIdx.x * blockDim.x + threadIdx.x) * 8;
    conv8(src, d, i);
}

// ---------------------------------------------------------------------------
// tf32 GEMM: CTA 128x128, 8 warps of 32x64 (mt=2, nt=8), BK=32, 2-stage.
// (R10 version — verified 71.5us, bit-exact)
// DEST: 0 = Cout fp32 [M,D]; 1 = g_Q (+RoPE,*SC_Q); 2 = g_K (+RoPE);
//       3 = g_V transposed [B,H,DK,S] s-permuted
// ---------------------------------------------------------------------------
#define BM 128
#define BN 128
#define BK 32
#define NIT (D_/BK)
#define TROW 40
#define TSB_OFF (BM*TROW)
#define TSTG ((BM*TROW + BN*TROW)*4)    // 40960 bytes
#define TSMEM (2*TSTG)                  // 81920 -> 2 CTA/SM

template<int DEST>
__global__ __launch_bounds__(256, 2)
void gemm_tf32(const float* __restrict__ A, const float* __restrict__ W,
               float* __restrict__ Cout, const int* __restrict__ tokpos)
{
    extern __shared__ __align__(16) char smem[];
    const int tid  = threadIdx.x;
    const int lane = tid & 31, w = tid >> 5;
    const int wm = (w & 3) * 32;
    const int wn = (w >> 2) * 64;
    const int m0 = blockIdx.x * BM;
    const int n0 = blockIdx.y * BN;
    const int rg = lane >> 2, tc = lane & 3;

    auto load_stage = [&](int st, int it) {
        float* s = (float*)(smem + st * TSTG);
        const int kk = it * BK;
#pragma unroll
        for (int i = 0; i < 4; i++) {           // A: 128 rows x 8 chunks
            int idx = tid + i * 256;
            int row = idx >> 3, ch = idx & 7;
            cp16(smem_u32(s + row * TROW + ch * 4),
                 A + (size_t)(m0 + row) * D_ + kk + ch * 4);
        }
        float* sB = s + TSB_OFF;
#pragma unroll
        for (int i = 0; i < 4; i++) {           // B: 128 rows x 8 chunks
            int idx = tid + i * 256;
            int row = idx >> 3, ch = idx & 7;
            cp16(smem_u32(sB + row * TROW + ch * 4),
                 W + (size_t)(n0 + row) * D_ + kk + ch * 4);
        }
    };

    float acc[2][8][4];
#pragma unroll
    for (int mt = 0; mt < 2; mt++)
#pragma unroll
        for (int nt = 0; nt < 8; nt++)
#pragma unroll
            for (int r = 0; r < 4; r++) acc[mt][nt][r] = 0.f;

    load_stage(0, 0); CP_COMMIT();
    load_stage(1, 1); CP_COMMIT();

    for (int it = 0; it < NIT; it++) {
        CP_WAIT1();
        __syncthreads();

        const float* s  = (const float*)(smem + (it & 1) * TSTG);
        const float* sB = s + TSB_OFF;
#pragma unroll
        for (int ks = 0; ks < 4; ks++) {
            uint32_t a[2][4];
#pragma unroll
            for (int mt = 0; mt < 2; mt++) {
                const float* base = s + (wm + mt * 16 + rg) * TROW + ks * 8 + 2 * tc;
                uint2 r1 = *(const uint2*)(base);
                uint2 r2 = *(const uint2*)(base + 8 * TROW);
                a[mt][0] = r1.x; a[mt][1] = r2.x; a[mt][2] = r1.y; a[mt][3] = r2.y;
            }
#pragma unroll
            for (int nt = 0; nt < 8; nt++) {
                uint2 bb = *(const uint2*)(sB + (wn + nt * 8 + rg) * TROW + ks * 8 + 2 * tc);
#pragma unroll
                for (int mt = 0; mt < 2; mt++)
                    mma_tf32(acc[mt][nt], a[mt], bb.x, bb.y);
            }
        }
        __syncthreads();
        if (it + 2 < NIT) load_stage(it & 1, it + 2);
        CP_COMMIT();
    }

#pragma unroll
    for (int mt = 0; mt < 2; mt++) {
        const int r0 = m0 + wm + mt * 16 + (lane >> 2);
#pragma unroll
        for (int nt = 0; nt < 8; nt++) {
            const int ncol = n0 + wn + nt * 8 + (lane & 3) * 2;   // even
            if (DEST == 0) {
                *(float2*)(Cout + (size_t)r0 * D_ + ncol) =
                    make_float2(acc[mt][nt][0], acc[mt][nt][1]);
                *(float2*)(Cout + (size_t)(r0 + 8) * D_ + ncol) =
                    make_float2(acc[mt][nt][2], acc[mt][nt][3]);
            } else if (DEST == 3) {
                const int h = ncol >> 6, dk = ncol & 63;
#pragma unroll
                for (int rr = 0; rr < 2; rr++) {
                    const int m = r0 + rr * 8;
                    const int bb = m >> 11, ss = m & (S_ - 1);
                    const int sp = (ss & ~7) + PERM8(ss & 7);
                    size_t base = ((size_t)(bb * H_ + h)) * DK_ * S_;
                    g_V[base + (size_t)dk * S_ + sp]       = tf32r(acc[mt][nt][2 * rr]);
                    g_V[base + (size_t)(dk + 1) * S_ + sp] = tf32r(acc[mt][nt][2 * rr + 1]);
                }
            } else {
                float* Dst = (DEST == 1) ? g_Q : g_K;
                const int h = ncol >> 6, dk = ncol & 63;
                const int dg = dk & ~7, dl = dk & 7;
                const int p0 = dg + PERM8(dl);
                const int p1 = dg + PERM8(dl + 1);
                const float fr = powf(10000.f, -(float)dk / 64.f);
#pragma unroll
                for (int rr = 0; rr < 2; rr++) {
                    const int m = r0 + rr * 8;
                    const int bb = m >> 11, ss = m & (S_ - 1);
                    const float pos = (float)tokpos[ss];
                    float sn, cs;
                    sincosf(pos * fr, &sn, &cs);
                    float e  = acc[mt][nt][2 * rr];
                    float od = acc[mt][nt][2 * rr + 1];
                    float v0 = e * cs - od * sn;
                    float v1 = e * sn + od * cs;
                    if (DEST == 1) { v0 *= SC_Q; v1 *= SC_Q; }
                    size_t ib = (((size_t)(bb * H_ + h)) * S_ + ss) * DK_;
                    Dst[ib + p0] = tf32r(v0);
                    Dst[ib + p1] = tf32r(v1);
                }
            }
        }
    }
}

// ---------------------------------------------------------------------------
// Flash attention (R8 version — verified ~150us, bit-exact).
// Single-pass tf32, CTA = 64q x 64kv, 4 warps, 2 CTA/SM.
// ---------------------------------------------------------------------------
#define AST 72                               // smem row stride (floats)
#define OKV0 (64*AST)
#define OP   (64*AST + 2*2*64*AST)           // = 23040
#define ATT_FLOATS (OP + 64*AST)             // 27648
#define ATT_SMEM (ATT_FLOATS*4)              // 110592 -> 2 CTA/SM

__global__ __launch_bounds__(128)
void attn_tf32()
{
    extern __shared__ __align__(16) float sm[];
    const int tid = threadIdx.x;
    const int lane = tid & 31, w = tid >> 5;
    const int rg = lane >> 2, tc = lane & 3;
    const int qt = (int)(gridDim.x - 1 - blockIdx.x);
    const int h  = blockIdx.y, b = blockIdx.z;
    const int q0 = qt * 64;
    const size_t gqk = ((size_t)(b * H_ + h)) * S_ * DK_;
    const size_t gvt = ((size_t)(b * H_ + h)) * DK_ * S_;

#pragma unroll
    for (int i = 0; i < 8; i++) {
        int idx = tid + i * 128;
        int r = idx >> 4, ch = idx & 15;
        cp16(smem_u32(sm + r * AST + ch * 4),
             g_Q + gqk + (size_t)(q0 + r) * DK_ + ch * 4);
    }
    auto load_kv = [&](int st, int kt) {
        float* sK = sm + OKV0 + st * (2 * 64 * AST);
        float* sV = sK + 64 * AST;
#pragma unroll
        for (int i = 0; i < 8; i++) {
            int idx = tid + i * 128;
            int r = idx >> 4, ch = idx & 15;
            cp16(smem_u32(sK + r * AST + ch * 4),
                 g_K + gqk + (size_t)(kt * 64 + r) * DK_ + ch * 4);
            cp16(smem_u32(sV + r * AST + ch * 4),
                 g_V + gvt + (size_t)r * S_ + kt * 64 + ch * 4);
        }
    };
    load_kv(0, 0); CP_COMMIT();
    if (qt >= 1) load_kv(1, 1);
    CP_COMMIT();

    CP_WAIT1();
    __syncthreads();

    // preload Q fragments (fixed across kv tiles); permuted pairs
    uint32_t qf[8][4];
    {
        const float* q = sm + (w * 16 + rg) * AST + 2 * tc;
#pragma unroll
        for (int ks = 0; ks < 8; ks++) {
            uint2 r1 = *(const uint2*)(q + ks * 8);
            uint2 r2 = *(const uint2*)(q + 8 * AST + ks * 8);
            qf[ks][0] = r1.x; qf[ks][1] = r2.x; qf[ks][2] = r1.y; qf[ks][3] = r2.y;
        }
    }

    float o[8][4];
#pragma unroll
    for (int d = 0; d < 8; d++)
#pragma unroll
        for (int r = 0; r < 4; r++) o[d][r] = 0.f;
    float mi0 = -1e30f, mi1 = -1e30f, li0 = 0.f, li1 = 0.f;
    const int row_lo = w * 16 + rg;
    const int colx   = 2 * tc;
    const int pp0 = PERM8(colx);
    const int pp1 = PERM8(colx + 1);
    float* pwf = sm + OP + w * 16 * AST;

    for (int kt = 0; kt <= qt; kt++) {
        if (kt) { CP_WAIT1(); __syncthreads(); }
        const float* sK = sm + OKV0 + (kt & 1) * (2 * 64 * AST);
        const float* sV = sK + 64 * AST;

        // ---- S = Q K^T ----
        float s[8][4];
#pragma unroll
        for (int nt = 0; nt < 8; nt++)
#pragma unroll
            for (int r = 0; r < 4; r++) s[nt][r] = 0.f;
#pragma unroll
        for (int ks = 0; ks < 8; ks++)
#pragma unroll
            for (int nt = 0; nt < 8; nt++) {
                uint2 kb = *(const uint2*)(sK + (nt * 8 + rg) * AST + ks * 8 + 2 * tc);
                mma_tf32(s[nt], qf[ks], kb.x, kb.y);
            }

        if (kt == qt) {   // causal mask on diagonal tile
#pragma unroll
            for (int nt = 0; nt < 8; nt++) {
                const int c = nt * 8 + colx;
                if (c     > row_lo)     s[nt][0] = -1e30f;
                if (c + 1 > row_lo)     s[nt][1] = -1e30f;
                if (c     > row_lo + 8) s[nt][2] = -1e30f;
                if (c + 1 > row_lo + 8) s[nt][3] = -1e30f;
            }
        }

        // ---- online softmax (base-2; scale folded into Q) ----
        float r0 = -1e30f, r1 = -1e30f;
#pragma unroll
        for (int nt = 0; nt < 8; nt++) {
            r0 = fmaxf(r0, fmaxf(s[nt][0], s[nt][1]));
            r1 = fmaxf(r1, fmaxf(s[nt][2], s[nt][3]));
        }
        r0 = fmaxf(r0, __shfl_xor_sync(0xffffffffu, r0, 1));
        r0 = fmaxf(r0, __shfl_xor_sync(0xffffffffu, r0, 2));
        r1 = fmaxf(r1, __shfl_xor_sync(0xffffffffu, r1, 1));
        r1 = fmaxf(r1, __shfl_xor_sync(0xffffffffu, r1, 2));
        const float mn0 = fmaxf(mi0, r0), mn1 = fmaxf(mi1, r1);
        const float c0 = ex2f(mi0 - mn0), c1 = ex2f(mi1 - mn1);
        float sum0 = 0.f, sum1 = 0.f;
#pragma unroll
        for (int nt = 0; nt < 8; nt++) {
            s[nt][0] = ex2f(s[nt][0] - mn0);
            s[nt][1] = ex2f(s[nt][1] - mn0);
            s[nt][2] = ex2f(s[nt][2] - mn1);
            s[nt][3] = ex2f(s[nt][3] - mn1);
            sum0 += s[nt][0] + s[nt][1];
            sum1 += s[nt][2] + s[nt][3];
        }
        sum0 += __shfl_xor_sync(0xffffffffu, sum0, 1);
        sum0 += __shfl_xor_sync(0xffffffffu, sum0, 2);
        sum1 += __shfl_xor_sync(0xffffffffu, sum1, 1);
        sum1 += __shfl_xor_sync(0xffffffffu, sum1, 2);
        li0 = li0 * c0 + sum0; li1 = li1 * c1 + sum1;
        mi0 = mn0; mi1 = mn1;
#pragma unroll
        for (int d = 0; d < 8; d++) {
            o[d][0] *= c0; o[d][1] *= c0; o[d][2] *= c1; o[d][3] *= c1;
        }

        // ---- stage P (tf32, s-permuted) in per-warp smem ----
#pragma unroll
        for (int nt = 0; nt < 8; nt++) {
            float* pr0 = pwf + rg * AST + nt * 8;
            float* pr1 = pwf + (rg + 8) * AST + nt * 8;
            pr0[pp0] = tf32r(s[nt][0]); pr0[pp1] = tf32r(s[nt][1]);
            pr1[pp0] = tf32r(s[nt][2]); pr1[pp1] = tf32r(s[nt][3]);
        }
        __syncwarp();

        // ---- O += P V ----
#pragma unroll
        for (int ks = 0; ks < 8; ks++) {
            uint32_t a[4];
            const float* pb = pwf + rg * AST + ks * 8 + 2 * tc;
            uint2 r1v = *(const uint2*)(pb);
            uint2 r2v = *(const uint2*)(pb + 8 * AST);
            a[0] = r1v.x; a[1] = r2v.x; a[2] = r1v.y; a[3] = r2v.y;
#pragma unroll
            for (int nt = 0; nt < 8; nt++) {
                uint2 vb = *(const uint2*)(sV + (nt * 8 + rg) * AST + ks * 8 + 2 * tc);
                mma_tf32(o[nt], a, vb.x, vb.y);
            }
        }

        __syncthreads();
        if (kt + 2 <= qt) load_kv(kt & 1, kt + 2);
        CP_COMMIT();
    }

    // ---- epilogue: normalize, write tf32 k-permuted [B,S,H*DK] ----
    const float inv0 = 1.f / li0, inv1 = 1.f / li1;
    const int grow0 = q0 + row_lo;
    const int op0 = PERM8(colx);
    const int op1 = PERM8(colx + 1);
#pragma unroll
    for (int d = 0; d < 8; d++) {
        const int cb = h * 64 + d * 8;
        float* a0 = g_AOt + ((size_t)b * S_ + grow0) * D_ + cb;
        float* a1 = g_AOt + ((size_t)b * S_ + grow0 + 8) * D_ + cb;
        a0[op0] = tf32r(o[d][0] * inv0); a0[op1] = tf32r(o[d][1] * inv0);
        a1[op0] = tf32r(o[d][2] * inv1); a1[op1] = tf32r(o[d][3] * inv1);
    }
}

// ---------------------------------------------------------------------------
// Host
// ---------------------------------------------------------------------------
extern "C" void kernel_launch(void* const* d_in, const int* in_sizes, int n_in,
                              void* d_out, int out_size)
{
    const float* x  = (const float*)d_in[0];
    const float* qw = (const float*)d_in[1];
    const float* kw = (const float*)d_in[2];
    const float* vw = (const float*)d_in[3];
    const float* ow = (const float*)d_in[4];
    const int*   tp = (const int*)d_in[6];
    float* out = (float*)d_out;

    void *xt, *wt, *aot;
    cudaGetSymbolAddress(&xt,  g_Xt);
    cudaGetSymbolAddress(&wt,  g_Wt);
    cudaGetSymbolAddress(&aot, g_AOt);
    float* Xt  = (float*)xt;
    float* Wt  = (float*)wt;
    float* AOt = (float*)aot;

    conv_x<<<M_*D_/8/256, 256>>>(x, Xt);
    dim3 wgrid(D_*D_/8/256, 4);
    conv_w4<<<wgrid, 256>>>(qw, kw, vw, ow, Wt);

    cudaFuncSetAttribute(gemm_tf32<0>, cudaFuncAttributeMaxDynamicSharedMemorySize, TSMEM);
    cudaFuncSetAttribute(gemm_tf32<1>, cudaFuncAttributeMaxDynamicSharedMemorySize, TSMEM);
    cudaFuncSetAttribute(gemm_tf32<2>, cudaFuncAttributeMaxDynamicSharedMemorySize, TSMEM);
    cudaFuncSetAttribute(gemm_tf32<3>, cudaFuncAttributeMaxDynamicSharedMemorySize, TSMEM);
    cudaFuncSetAttribute(attn_tf32, cudaFuncAttributeMaxDynamicSharedMemorySize, ATT_SMEM);

    dim3 ggrid(M_ / BM, D_ / BN);   // (32, 8)
    gemm_tf32<1><<<ggrid, 256, TSMEM>>>(Xt, Wt,                   nullptr, tp);
    gemm_tf32<2><<<ggrid, 256, TSMEM>>>(Xt, Wt + 1*(size_t)D_*D_, nullptr, tp);
    gemm_tf32<3><<<ggrid, 256, TSMEM>>>(Xt, Wt + 2*(size_t)D_*D_, nullptr, tp);

    dim3 agrid(S_ / 64, H_, B_);    // (32, 16, 2)
    attn_tf32<<<agrid, 128, ATT_SMEM>>>();

    gemm_tf32<0><<<ggrid, 256, TSMEM>>>(AOt, Wt + 3*(size_t)D_*D_, out, tp);
}

// round 12
// speedup vs baseline: 1.2262x; 1.0688x over previous
#include <cuda_runtime.h>
#include <math.h>
#include <stdint.h>

#define B_  2
#define S_  2048
#define D_  1024
#define H_  16
#define DK_ 64
#define M_  (B_*S_)

// k-group permutation (attention operands only): position 2i <-> logical i,
// 2i+1 <-> logical i+4. Applied to both mma operands -> bit-exact.
#define PERM8(j) (((j) < 4) ? 2*(j) : 2*(j) - 7)

// ---------------------------------------------------------------------------
// Scratch (__device__ globals; allocation-free contract)
// ---------------------------------------------------------------------------
__device__ __align__(16) float g_Xt [M_*D_];            // X tf32 (plain)
__device__ __align__(16) float g_Wt [4*(size_t)D_*D_];  // weights tf32 (plain)
__device__ __align__(16) float g_AOt[M_*D_];            // attn out tf32 (plain)
__device__ __align__(16) float g_Q[B_*H_*S_*DK_];       // [B,H,S,DK] dk-permuted, *log2(e)/8
__device__ __align__(16) float g_K[B_*H_*S_*DK_];       // [B,H,S,DK] dk-permuted
__device__ __align__(16) float g_V[B_*H_*S_*DK_];       // [B,H,DK,S] s-permuted

// ---------------------------------------------------------------------------
// PTX wrappers
// ---------------------------------------------------------------------------
__device__ __forceinline__ uint32_t smem_u32(const void* p) {
    uint32_t a;
    asm("{ .reg .u64 t; cvta.to.shared.u64 t, %1; cvt.u32.u64 %0, t; }"
        : "=r"(a) : "l"(p));
    return a;
}
__device__ __forceinline__ void cp16(uint32_t dst, const void* src) {
    asm volatile("cp.async.cg.shared.global [%0], [%1], 16;"
                 :: "r"(dst), "l"(src));
}
#define CP_COMMIT() asm volatile("cp.async.commit_group;")
#define CP_WAIT1()  asm volatile("cp.async.wait_group 1;")

// ldmatrix x4: for tf32 data, each 8x8 b16 matrix = 8 rows x 4 tf32.
// Thread t receives tf32 element (row t/4, col t%4) of each matrix.
__device__ __forceinline__ void ldm4(uint32_t (&a)[4], uint32_t addr) {
    asm volatile("ldmatrix.sync.aligned.m8n8.x4.shared.b16 {%0,%1,%2,%3}, [%4];"
                 : "=r"(a[0]), "=r"(a[1]), "=r"(a[2]), "=r"(a[3]) : "r"(addr));
}
__device__ __forceinline__ void mma_tf32(float (&d)[4], const uint32_t (&a)[4],
                                         uint32_t b0, uint32_t b1) {
    asm volatile(
        "mma.sync.aligned.m16n8k8.row.col.f32.tf32.tf32.f32 "
        "{%0,%1,%2,%3}, {%4,%5,%6,%7}, {%8,%9}, {%0,%1,%2,%3};"
        : "+f"(d[0]), "+f"(d[1]), "+f"(d[2]), "+f"(d[3])
        : "r"(a[0]), "r"(a[1]), "r"(a[2]), "r"(a[3]), "r"(b0), "r"(b1));
}
__device__ __forceinline__ float ex2f(float x) {
    float y; asm("ex2.approx.f32 %0, %1;" : "=f"(y) : "f"(x)); return y;
}
__device__ __forceinline__ float tf32r(float x) {
    uint32_t r; asm("cvt.rna.tf32.f32 %0, %1;" : "=r"(r) : "f"(x));
    return __uint_as_float(r);
}

#define SC_Q 0.18033688011112042f   // log2(e)/8, folded into Q at projection

// ---------------------------------------------------------------------------
// Prep: tf32-round (rna; mma truncates raw fp32). Plain layout.
// ---------------------------------------------------------------------------
__device__ __forceinline__ void conv8(const float* src, float* dst, size_t i) {
    float4 v = *(const float4*)(src + i);
    float4 w = *(const float4*)(src + i + 4);
    *(float4*)(dst + i)     = make_float4(tf32r(v.x), tf32r(v.y), tf32r(v.z), tf32r(v.w));
    *(float4*)(dst + i + 4) = make_float4(tf32r(w.x), tf32r(w.y), tf32r(w.z), tf32r(w.w));
}
__global__ __launch_bounds__(256)
void conv_x(const float* __restrict__ src, float* __restrict__ dst)
{
    size_t i = ((size_t)blockIdx.x * blockDim.x + threadIdx.x) * 8;
    conv8(src, dst, i);
}
__global__ __launch_bounds__(256)
void conv_w4(const float* __restrict__ w0, const float* __restrict__ w1,
             const float* __restrict__ w2, const float* __restrict__ w3,
             float* __restrict__ dst)
{
    const float* srcs[4] = {w0, w1, w2, w3};
    const float* src = srcs[blockIdx.y];
    float* d = dst + (size_t)blockIdx.y * D_ * D_;
    size_t i = ((size_t)blockIdx.x * blockDim.x + threadIdx.x) * 8;
    conv8(src, d, i);
}

// ---------------------------------------------------------------------------
// tf32 GEMM: CTA 128x128, 8 warps of 32x64, BK=32.
// ldmatrix fragment loads, 3-stage cp.async, ONE barrier per iter, 2 CTA/SM.
// TROW=36 (stride 144B = 16 mod 128 -> ldmatrix phase conflict-free).
// DEST: 0 = Cout fp32 [M,D]; 1 = g_Q (+RoPE,*SC_Q); 2 = g_K (+RoPE);
//       3 = g_V transposed [B,H,DK,S] s-permuted
// ---------------------------------------------------------------------------
#define BM 128
#define BN 128
#define BK 32
#define NIT (D_/BK)
#define TROW 36
#define TROWB 144
#define TSB_OFFB (BM*TROWB)             // 18432 B
#define TSTG ((BM+BN)*TROWB)            // 36864 B
#define NSTG 3
#define TSMEM (NSTG*TSTG)               // 110592 -> 2 CTA/SM

template<int DEST>
__global__ __launch_bounds__(256, 2)
void gemm_tf32(const float* __restrict__ A, const float* __restrict__ W,
               float* __restrict__ Cout, const int* __restrict__ tokpos)
{
    extern __shared__ __align__(16) char smem[];
    const int tid  = threadIdx.x;
    const int lane = tid & 31, w = tid >> 5;
    const int wm = (w & 3) * 32;
    const int wn = (w >> 2) * 64;
    const int m0 = blockIdx.x * BM;
    const int n0 = blockIdx.y * BN;

    auto load_stage = [&](int st, int it) {
        float* s = (float*)(smem + st * TSTG);
        const int kk = it * BK;
#pragma unroll
        for (int i = 0; i < 4; i++) {           // A: 128 rows x 8 chunks
            int idx = tid + i * 256;
            int row = idx >> 3, ch = idx & 7;
            cp16(smem_u32(s + row * TROW + ch * 4),
                 A + (size_t)(m0 + row) * D_ + kk + ch * 4);
        }
        float* sB = s + BM * TROW;
#pragma unroll
        for (int i = 0; i < 4; i++) {           // B: 128 rows x 8 chunks
            int idx = tid + i * 256;
            int row = idx >> 3, ch = idx & 7;
            cp16(smem_u32(sB + row * TROW + ch * 4),
                 W + (size_t)(n0 + row) * D_ + kk + ch * 4);
        }
    };

    float acc[2][8][4];
#pragma unroll
    for (int mt = 0; mt < 2; mt++)
#pragma unroll
        for (int nt = 0; nt < 8; nt++)
#pragma unroll
            for (int r = 0; r < 4; r++) acc[mt][nt][r] = 0.f;

    load_stage(0, 0); CP_COMMIT();
    load_stage(1, 1); CP_COMMIT();

    // ldmatrix per-lane addresses (byte offsets within a stage)
    const uint32_t sbase = smem_u32(smem);
    const int ri = lane & 7, mi = lane >> 3;
    // A x4: m0=rows[0:8)k[0:4), m1=rows[8:16)k[0:4), m2=rows[0:8)k[4:8), m3=rows[8:16)k[4:8)
    const uint32_t a_lm = (uint32_t)((wm + ri + 8 * (mi & 1)) * TROWB + (mi >> 1) * 16);
    // B x4 (two n-blocks): m0=n[0:8)k[0:4), m1=n[0:8)k[4:8), m2=n[8:16)k[0:4), m3=n[8:16)k[4:8)
    const uint32_t b_lm = (uint32_t)(TSB_OFFB + (wn + ri + 8 * (mi >> 1)) * TROWB + (mi & 1) * 16);

    for (int it = 0; it < NIT; it++) {
        CP_WAIT1();
        __syncthreads();
        if (it + 2 < NIT) load_stage((it + 2) % NSTG, it + 2);
        CP_COMMIT();

        const uint32_t st = sbase + (uint32_t)((it % NSTG) * TSTG);
#pragma unroll
        for (int ks = 0; ks < 4; ks++) {
            uint32_t a0[4], a1[4];
            ldm4(a0, st + a_lm + ks * 32);
            ldm4(a1, st + a_lm + 16 * TROWB + ks * 32);
#pragma unroll
            for (int j = 0; j < 4; j++) {
                uint32_t bb[4];
                ldm4(bb, st + b_lm + j * 16 * TROWB + ks * 32);
                mma_tf32(acc[0][2 * j],     a0, bb[0], bb[1]);
                mma_tf32(acc[1][2 * j],     a1, bb[0], bb[1]);
                mma_tf32(acc[0][2 * j + 1], a0, bb[2], bb[3]);
                mma_tf32(acc[1][2 * j + 1], a1, bb[2], bb[3]);
            }
        }
    }

#pragma unroll
    for (int mt = 0; mt < 2; mt++) {
        const int r0 = m0 + wm + mt * 16 + (lane >> 2);
#pragma unroll
        for (int nt = 0; nt < 8; nt++) {
            const int ncol = n0 + wn + nt * 8 + (lane & 3) * 2;   // even
            if (DEST == 0) {
                *(float2*)(Cout + (size_t)r0 * D_ + ncol) =
                    make_float2(acc[mt][nt][0], acc[mt][nt][1]);
                *(float2*)(Cout + (size_t)(r0 + 8) * D_ + ncol) =
                    make_float2(acc[mt][nt][2], acc[mt][nt][3]);
            } else if (DEST == 3) {
                const int h = ncol >> 6, dk = ncol & 63;
#pragma unroll
                for (int rr = 0; rr < 2; rr++) {
                    const int m = r0 + rr * 8;
                    const int bb = m >> 11, ss = m & (S_ - 1);
                    const int sp = (ss & ~7) + PERM8(ss & 7);
                    size_t base = ((size_t)(bb * H_ + h)) * DK_ * S_;
                    g_V[base + (size_t)dk * S_ + sp]       = tf32r(acc[mt][nt][2 * rr]);
                    g_V[base + (size_t)(dk + 1) * S_ + sp] = tf32r(acc[mt][nt][2 * rr + 1]);
                }
            } else {
                float* Dst = (DEST == 1) ? g_Q : g_K;
                const int h = ncol >> 6, dk = ncol & 63;
                const int dg = dk & ~7, dl = dk & 7;
                const int p0 = dg + PERM8(dl);
                const int p1 = dg + PERM8(dl + 1);
                const float fr = powf(10000.f, -(float)dk / 64.f);
#pragma unroll
                for (int rr = 0; rr < 2; rr++) {
                    const int m = r0 + rr * 8;
                    const int bb = m >> 11, ss = m & (S_ - 1);
                    const float pos = (float)tokpos[ss];
                    float sn, cs;
                    sincosf(pos * fr, &sn, &cs);
                    float e  = acc[mt][nt][2 * rr];
                    float od = acc[mt][nt][2 * rr + 1];
                    float v0 = e * cs - od * sn;
                    float v1 = e * sn + od * cs;
                    if (DEST == 1) { v0 *= SC_Q; v1 *= SC_Q; }
                    size_t ib = (((size_t)(bb * H_ + h)) * S_ + ss) * DK_;
                    Dst[ib + p0] = tf32r(v0);
                    Dst[ib + p1] = tf32r(v1);
                }
            }
        }
    }
}

// ---------------------------------------------------------------------------
// Flash attention (R11 version, verified): single-pass tf32, CTA 64q x 64kv,
// 4 warps, 2 CTA/SM. Only change: AOt epilogue writes PLAIN layout.
// ---------------------------------------------------------------------------
#define AST 72                               // smem row stride (floats)
#define OKV0 (64*AST)
#define OP   (64*AST + 2*2*64*AST)           // = 23040
#define ATT_FLOATS (OP + 64*AST)             // 27648
#define ATT_SMEM (ATT_FLOATS*4)              // 110592 -> 2 CTA/SM

__global__ __launch_bounds__(128)
void attn_tf32()
{
    extern __shared__ __align__(16) float sm[];
    const int tid = threadIdx.x;
    const int lane = tid & 31, w = tid >> 5;
    const int rg = lane >> 2, tc = lane & 3;
    const int qt = (int)(gridDim.x - 1 - blockIdx.x);
    const int h  = blockIdx.y, b = blockIdx.z;
    const int q0 = qt * 64;
    const size_t gqk = ((size_t)(b * H_ + h)) * S_ * DK_;
    const size_t gvt = ((size_t)(b * H_ + h)) * DK_ * S_;

#pragma unroll
    for (int i = 0; i < 8; i++) {
        int idx = tid + i * 128;
        int r = idx >> 4, ch = idx & 15;
        cp16(smem_u32(sm + r * AST + ch * 4),
             g_Q + gqk + (size_t)(q0 + r) * DK_ + ch * 4);
    }
    auto load_kv = [&](int st, int kt) {
        float* sK = sm + OKV0 + st * (2 * 64 * AST);
        float* sV = sK + 64 * AST;
#pragma unroll
        for (int i = 0; i < 8; i++) {
            int idx = tid + i * 128;
            int r = idx >> 4, ch = idx & 15;
            cp16(smem_u32(sK + r * AST + ch * 4),
                 g_K + gqk + (size_t)(kt * 64 + r) * DK_ + ch * 4);
            cp16(smem_u32(sV + r * AST + ch * 4),
                 g_V + gvt + (size_t)r * S_ + kt * 64 + ch * 4);
        }
    };
    load_kv(0, 0); CP_COMMIT();
    if (qt >= 1) load_kv(1, 1);
    CP_COMMIT();

    CP_WAIT1();
    __syncthreads();

    // preload Q fragments (fixed across kv tiles); permuted pairs
    uint32_t qf[8][4];
    {
        const float* q = sm + (w * 16 + rg) * AST + 2 * tc;
#pragma unroll
        for (int ks = 0; ks < 8; ks++) {
            uint2 r1 = *(const uint2*)(q + ks * 8);
            uint2 r2 = *(const uint2*)(q + 8 * AST + ks * 8);
            qf[ks][0] = r1.x; qf[ks][1] = r2.x; qf[ks][2] = r1.y; qf[ks][3] = r2.y;
        }
    }

    float o[8][4];
#pragma unroll
    for (int d = 0; d < 8; d++)
#pragma unroll
        for (int r = 0; r < 4; r++) o[d][r] = 0.f;
    float mi0 = -1e30f, mi1 = -1e30f, li0 = 0.f, li1 = 0.f;
    const int row_lo = w * 16 + rg;
    const int colx   = 2 * tc;
    const int pp0 = PERM8(colx);
    const int pp1 = PERM8(colx + 1);
    float* pwf = sm + OP + w * 16 * AST;

    for (int kt = 0; kt <= qt; kt++) {
        if (kt) { CP_WAIT1(); __syncthreads(); }
        const float* sK = sm + OKV0 + (kt & 1) * (2 * 64 * AST);
        const float* sV = sK + 64 * AST;

        // ---- S = Q K^T ----
        float s[8][4];
#pragma unroll
        for (int nt = 0; nt < 8; nt++)
#pragma unroll
            for (int r = 0; r < 4; r++) s[nt][r] = 0.f;
#pragma unroll
        for (int ks = 0; ks < 8; ks++)
#pragma unroll
            for (int nt = 0; nt < 8; nt++) {
                uint2 kb = *(const uint2*)(sK + (nt * 8 + rg) * AST + ks * 8 + 2 * tc);
                mma_tf32(s[nt], qf[ks], kb.x, kb.y);
            }

        if (kt == qt) {   // causal mask on diagonal tile
#pragma unroll
            for (int nt = 0; nt < 8; nt++) {
                const int c = nt * 8 + colx;
                if (c     > row_lo)     s[nt][0] = -1e30f;
                if (c + 1 > row_lo)     s[nt][1] = -1e30f;
                if (c     > row_lo + 8) s[nt][2] = -1e30f;
                if (c + 1 > row_lo + 8) s[nt][3] = -1e30f;
            }
        }

        // ---- online softmax (base-2; scale folded into Q) ----
        float r0 = -1e30f, r1 = -1e30f;
#pragma unroll
        for (int nt = 0; nt < 8; nt++) {
            r0 = fmaxf(r0, fmaxf(s[nt][0], s[nt][1]));
            r1 = fmaxf(r1, fmaxf(s[nt][2], s[nt][3]));
        }
        r0 = fmaxf(r0, __shfl_xor_sync(0xffffffffu, r0, 1));
        r0 = fmaxf(r0, __shfl_xor_sync(0xffffffffu, r0, 2));
        r1 = fmaxf(r1, __shfl_xor_sync(0xffffffffu, r1, 1));
        r1 = fmaxf(r1, __shfl_xor_sync(0xffffffffu, r1, 2));
        const float mn0 = fmaxf(mi0, r0), mn1 = fmaxf(mi1, r1);
        const float c0 = ex2f(mi0 - mn0), c1 = ex2f(mi1 - mn1);
        float sum0 = 0.f, sum1 = 0.f;
#pragma unroll
        for (int nt = 0; nt < 8; nt++) {
            s[nt][0] = ex2f(s[nt][0] - mn0);
            s[nt][1] = ex2f(s[nt][1] - mn0);
            s[nt][2] = ex2f(s[nt][2] - mn1);
            s[nt][3] = ex2f(s[nt][3] - mn1);
            sum0 += s[nt][0] + s[nt][1];
            sum1 += s[nt][2] + s[nt][3];
        }
        sum0 += __shfl_xor_sync(0xffffffffu, sum0, 1);
        sum0 += __shfl_xor_sync(0xffffffffu, sum0, 2);
        sum1 += __shfl_xor_sync(0xffffffffu, sum1, 1);
        sum1 += __shfl_xor_sync(0xffffffffu, sum1, 2);
        li0 = li0 * c0 + sum0; li1 = li1 * c1 + sum1;
        mi0 = mn0; mi1 = mn1;
#pragma unroll
        for (int d = 0; d < 8; d++) {
            o[d][0] *= c0; o[d][1] *= c0; o[d][2] *= c1; o[d][3] *= c1;
        }

        // ---- stage P (tf32, s-permuted) in per-warp smem ----
#pragma unroll
        for (int nt = 0; nt < 8; nt++) {
            float* pr0 = pwf + rg * AST + nt * 8;
            float* pr1 = pwf + (rg + 8) * AST + nt * 8;
            pr0[pp0] = tf32r(s[nt][0]); pr0[pp1] = tf32r(s[nt][1]);
            pr1[pp0] = tf32r(s[nt][2]); pr1[pp1] = tf32r(s[nt][3]);
        }
        __syncwarp();

        // ---- O += P V ----
#pragma unroll
        for (int ks = 0; ks < 8; ks++) {
            uint32_t a[4];
            const float* pb = pwf + rg * AST + ks * 8 + 2 * tc;
            uint2 r1v = *(const uint2*)(pb);
            uint2 r2v = *(const uint2*)(pb + 8 * AST);
            a[0] = r1v.x; a[1] = r2v.x; a[2] = r1v.y; a[3] = r2v.y;
#pragma unroll
            for (int nt = 0; nt < 8; nt++) {
                uint2 vb = *(const uint2*)(sV + (nt * 8 + rg) * AST + ks * 8 + 2 * tc);
                mma_tf32(o[nt], a, vb.x, vb.y);
            }
        }

        __syncthreads();
        if (kt + 2 <= qt) load_kv(kt & 1, kt + 2);
        CP_COMMIT();
    }

    // ---- epilogue: normalize, write tf32 PLAIN [B,S,H*DK] (ldmatrix GEMM) ----
    const float inv0 = 1.f / li0, inv1 = 1.f / li1;
    const int grow0 = q0 + row_lo;
#pragma unroll
    for (int d = 0; d < 8; d++) {
        const int cb = h * 64 + d * 8 + colx;
        *(float2*)(g_AOt + ((size_t)b * S_ + grow0) * D_ + cb) =
            make_float2(tf32r(o[d][0] * inv0), tf32r(o[d][1] * inv0));
        *(float2*)(g_AOt + ((size_t)b * S_ + grow0 + 8) * D_ + cb) =
            make_float2(tf32r(o[d][2] * inv1), tf32r(o[d][3] * inv1));
    }
}

// ---------------------------------------------------------------------------
// Host
// ---------------------------------------------------------------------------
extern "C" void kernel_launch(void* const* d_in, const int* in_sizes, int n_in,
                              void* d_out, int out_size)
{
    const float* x  = (const float*)d_in[0];
    const float* qw = (const float*)d_in[1];
    const float* kw = (const float*)d_in[2];
    const float* vw = (const float*)d_in[3];
    const float* ow = (const float*)d_in[4];
    const int*   tp = (const int*)d_in[6];
    float* out = (float*)d_out;

    void *xt, *wt, *aot;
    cudaGetSymbolAddress(&xt,  g_Xt);
    cudaGetSymbolAddress(&wt,  g_Wt);
    cudaGetSymbolAddress(&aot, g_AOt);
    float* Xt  = (float*)xt;
    float* Wt  = (float*)wt;
    float* AOt = (float*)aot;

    conv_x<<<M_*D_/8/256, 256>>>(x, Xt);
    dim3 wgrid(D_*D_/8/256, 4);
    conv_w4<<<wgrid, 256>>>(qw, kw, vw, ow, Wt);

    cudaFuncSetAttribute(gemm_tf32<0>, cudaFuncAttributeMaxDynamicSharedMemorySize, TSMEM);
    cudaFuncSetAttribute(gemm_tf32<1>, cudaFuncAttributeMaxDynamicSharedMemorySize, TSMEM);
    cudaFuncSetAttribute(gemm_tf32<2>, cudaFuncAttributeMaxDynamicSharedMemorySize, TSMEM);
    cudaFuncSetAttribute(gemm_tf32<3>, cudaFuncAttributeMaxDynamicSharedMemorySize, TSMEM);
    cudaFuncSetAttribute(attn_tf32, cudaFuncAttributeMaxDynamicSharedMemorySize, ATT_SMEM);

    dim3 ggrid(M_ / BM, D_ / BN);   // (32, 8)
    gemm_tf32<1><<<ggrid, 256, TSMEM>>>(Xt, Wt,                   nullptr, tp);
    gemm_tf32<2><<<ggrid, 256, TSMEM>>>(Xt, Wt + 1*(size_t)D_*D_, nullptr, tp);
    gemm_tf32<3><<<ggrid, 256, TSMEM>>>(Xt, Wt + 2*(size_t)D_*D_, nullptr, tp);

    dim3 agrid(S_ / 64, H_, B_);    // (32, 16, 2)
    attn_tf32<<<agrid, 128, ATT_SMEM>>>();

    gemm_tf32<0><<<ggrid, 256, TSMEM>>>(AOt, Wt + 3*(size_t)D_*D_, out, tp);
}

// round 13
// speedup vs baseline: 2.2540x; 1.8382x over previous
#include <cuda_runtime.h>
#include <cuda_fp16.h>
#include <math.h>
#include <stdint.h>

#define B_  2
#define S_  2048
#define D_  1024
#define H_  16
#define DK_ 64
#define M_  (B_*S_)

// ---------------------------------------------------------------------------
// Scratch (__device__ globals; allocation-free contract)
// ---------------------------------------------------------------------------
__device__ __align__(16) __half g_Xh [M_*D_];            // X fp16
__device__ __align__(16) __half g_Wh [4*(size_t)D_*D_];  // weights fp16 [mat][n][k]
__device__ __align__(16) __half g_AOh[M_*D_];            // attn out fp16 [B,S,D]
__device__ __align__(16) __half g_Q[B_*H_*S_*DK_];       // [B,H,S,DK], *log2(e)/8
__device__ __align__(16) __half g_K[B_*H_*S_*DK_];       // [B,H,S,DK]
__device__ __align__(16) __half g_V[B_*H_*S_*DK_];       // [B,H,DK,S] (transposed)

// ---------------------------------------------------------------------------
// PTX wrappers
// ---------------------------------------------------------------------------
__device__ __forceinline__ uint32_t smem_u32(const void* p) {
    uint32_t a;
    asm("{ .reg .u64 t; cvta.to.shared.u64 t, %1; cvt.u32.u64 %0, t; }"
        : "=r"(a) : "l"(p));
    return a;
}
__device__ __forceinline__ void cp16(uint32_t dst, const void* src) {
    asm volatile("cp.async.cg.shared.global [%0], [%1], 16;"
                 :: "r"(dst), "l"(src));
}
#define CP_COMMIT() asm volatile("cp.async.commit_group;")
#define CP_WAIT1()  asm volatile("cp.async.wait_group 1;")

__device__ __forceinline__ void ldm4(uint32_t (&a)[4], uint32_t addr) {
    asm volatile("ldmatrix.sync.aligned.m8n8.x4.shared.b16 {%0,%1,%2,%3}, [%4];"
                 : "=r"(a[0]), "=r"(a[1]), "=r"(a[2]), "=r"(a[3]) : "r"(addr));
}
__device__ __forceinline__ void mma_f16(float (&d)[4], const uint32_t (&a)[4],
                                        uint32_t b0, uint32_t b1) {
    asm volatile(
        "mma.sync.aligned.m16n8k16.row.col.f32.f16.f16.f32 "
        "{%0,%1,%2,%3}, {%4,%5,%6,%7}, {%8,%9}, {%0,%1,%2,%3};"
        : "+f"(d[0]), "+f"(d[1]), "+f"(d[2]), "+f"(d[3])
        : "r"(a[0]), "r"(a[1]), "r"(a[2]), "r"(a[3]), "r"(b0), "r"(b1));
}
__device__ __forceinline__ float ex2f(float x) {
    float y; asm("ex2.approx.f32 %0, %1;" : "=f"(y) : "f"(x)); return y;
}
// pack two floats into f16x2: .lo = f16(a), .hi = f16(b)
__device__ __forceinline__ uint32_t packh2(float a, float b) {
    uint32_t r;
    asm("cvt.rn.f16x2.f32 %0, %1, %2;" : "=r"(r) : "f"(b), "f"(a));
    return r;
}

#define SC_Q 0.18033688011112042f   // log2(e)/8, folded into Q at projection

// ---------------------------------------------------------------------------
// Prep: fp32 -> fp16 (rn). Each thread converts 8 elements (16B store).
// ---------------------------------------------------------------------------
__device__ __forceinline__ void conv8h(const float* src, __half* dst, size_t i) {
    float4 v = *(const float4*)(src + i);
    float4 w = *(const float4*)(src + i + 4);
    uint4 r;
    r.x = packh2(v.x, v.y);
    r.y = packh2(v.z, v.w);
    r.z = packh2(w.x, w.y);
    r.w = packh2(w.z, w.w);
    *(uint4*)(dst + i) = r;
}
__global__ __launch_bounds__(256)
void conv_x(const float* __restrict__ src, __half* __restrict__ dst)
{
    size_t i = ((size_t)blockIdx.x * blockDim.x + threadIdx.x) * 8;
    conv8h(src, dst, i);
}
__global__ __launch_bounds__(256)
void conv_w4(const float* __restrict__ w0, const float* __restrict__ w1,
             const float* __restrict__ w2, const float* __restrict__ w3,
             __half* __restrict__ dst)
{
    const float* srcs[4] = {w0, w1, w2, w3};
    const float* src = srcs[blockIdx.y];
    __half* d = dst + (size_t)blockIdx.y * D_ * D_;
    size_t i = ((size_t)blockIdx.x * blockDim.x + threadIdx.x) * 8;
    conv8h(src, d, i);
}

// ---------------------------------------------------------------------------
// fp16 GEMM: C[m,n] = sum_k A[m,k]*W[n,k], fp32 accum.
// CTA 128x128, 8 warps of 32x64, BK=64 halves, 3-stage cp.async, 2 CTA/SM.
// Row stride 144B -> ldmatrix conflict-free. Per k16: 6 ldm.x4 : 16 mma.
// DEST: 0 = Cout fp32 [M,D]; 1 = g_Q (+RoPE,*SC_Q); 2 = g_K (+RoPE);
//       3 = g_V transposed [B,H,DK,S]
// ---------------------------------------------------------------------------
#define BM 128
#define BN 128
#define BK 64
#define NIT (D_/BK)                      // 16
#define HROWB 144                        // 64 halves padded to 144 bytes
#define TSB_OFFB (BM*HROWB)              // 18432
#define TSTG ((BM+BN)*HROWB)             // 36864 bytes
#define NSTG 3
#define TSMEM (NSTG*TSTG)                // 110592 -> 2 CTA/SM

template<int DEST>
__global__ __launch_bounds__(256, 2)
void gemm_f16(const __half* __restrict__ A, const __half* __restrict__ W,
              float* __restrict__ Cout, const int* __restrict__ tokpos)
{
    extern __shared__ __align__(16) char smem[];
    const int tid  = threadIdx.x;
    const int lane = tid & 31, w = tid >> 5;
    const int wm = (w & 3) * 32;
    const int wn = (w >> 2) * 64;
    const int m0 = blockIdx.x * BM;
    const int n0 = blockIdx.y * BN;

    auto load_stage = [&](int st, int it) {
        char* s = smem + st * TSTG;
        const int kk = it * BK;
#pragma unroll
        for (int i = 0; i < 4; i++) {           // A: 128 rows x 8 chunks(16B)
            int idx = tid + i * 256;
            int row = idx >> 3, ch = idx & 7;
            cp16(smem_u32(s + row * HROWB + ch * 16),
                 A + (size_t)(m0 + row) * D_ + kk + ch * 8);
        }
        char* sB = s + TSB_OFFB;
#pragma unroll
        for (int i = 0; i < 4; i++) {           // B: 128 rows x 8 chunks
            int idx = tid + i * 256;
            int row = idx >> 3, ch = idx & 7;
            cp16(smem_u32(sB + row * HROWB + ch * 16),
                 W + (size_t)(n0 + row) * D_ + kk + ch * 8);
        }
    };

    float acc[2][8][4];
#pragma unroll
    for (int mt = 0; mt < 2; mt++)
#pragma unroll
        for (int nt = 0; nt < 8; nt++)
#pragma unroll
            for (int r = 0; r < 4; r++) acc[mt][nt][r] = 0.f;

    load_stage(0, 0); CP_COMMIT();
    load_stage(1, 1); CP_COMMIT();

    // ldmatrix lane addresses (bytes within stage)
    const uint32_t sbase = smem_u32(smem);
    const int ri = lane & 7, mi = lane >> 3;
    // A x4: m0=r[0:8)k-lo, m1=r[8:16)k-lo, m2=r[0:8)k-hi, m3=r[8:16)k-hi
    const uint32_t a_lm = (uint32_t)((wm + (lane & 15)) * HROWB + ((lane >> 4) << 4));
    // B x4: m0=n[0:8)k-lo, m1=n[0:8)k-hi, m2=n[8:16)k-lo, m3=n[8:16)k-hi
    const uint32_t b_lm = (uint32_t)(TSB_OFFB + (wn + ri + 8 * (mi >> 1)) * HROWB
                                     + (mi & 1) * 16);

    for (int it = 0; it < NIT; it++) {
        CP_WAIT1();
        __syncthreads();
        if (it + 2 < NIT) load_stage((it + 2) % NSTG, it + 2);
        CP_COMMIT();

        const uint32_t st = sbase + (uint32_t)((it % NSTG) * TSTG);
#pragma unroll
        for (int ks = 0; ks < 4; ks++) {        // 4 k16 steps in BK=64
            uint32_t a0[4], a1[4];
            ldm4(a0, st + a_lm + ks * 32);
            ldm4(a1, st + a_lm + 16 * HROWB + ks * 32);
#pragma unroll
            for (int j = 0; j < 4; j++) {
                uint32_t bb[4];
                ldm4(bb, st + b_lm + j * 16 * HROWB + ks * 32);
                mma_f16(acc[0][2 * j],     a0, bb[0], bb[1]);
                mma_f16(acc[1][2 * j],     a1, bb[0], bb[1]);
                mma_f16(acc[0][2 * j + 1], a0, bb[2], bb[3]);
                mma_f16(acc[1][2 * j + 1], a1, bb[2], bb[3]);
            }
        }
    }

#pragma unroll
    for (int mt = 0; mt < 2; mt++) {
        const int r0 = m0 + wm + mt * 16 + (lane >> 2);
#pragma unroll
        for (int nt = 0; nt < 8; nt++) {
            const int ncol = n0 + wn + nt * 8 + (lane & 3) * 2;   // even
            if (DEST == 0) {
                *(float2*)(Cout + (size_t)r0 * D_ + ncol) =
                    make_float2(acc[mt][nt][0], acc[mt][nt][1]);
                *(float2*)(Cout + (size_t)(r0 + 8) * D_ + ncol) =
                    make_float2(acc[mt][nt][2], acc[mt][nt][3]);
            } else if (DEST == 3) {
                const int h = ncol >> 6, dk = ncol & 63;
#pragma unroll
                for (int rr = 0; rr < 2; rr++) {
                    const int m = r0 + rr * 8;
                    const int bb = m >> 11, ss = m & (S_ - 1);
                    size_t base = ((size_t)(bb * H_ + h)) * DK_ * S_;
                    g_V[base + (size_t)dk * S_ + ss] =
                        __float2half_rn(acc[mt][nt][2 * rr]);
                    g_V[base + (size_t)(dk + 1) * S_ + ss] =
                        __float2half_rn(acc[mt][nt][2 * rr + 1]);
                }
            } else {
                __half* Dst = (DEST == 1) ? g_Q : g_K;
                const int h = ncol >> 6, dk = ncol & 63;   // even: RoPE pair
                const float fr = powf(10000.f, -(float)dk / 64.f);
#pragma unroll
                for (int rr = 0; rr < 2; rr++) {
                    const int m = r0 + rr * 8;
                    const int bb = m >> 11, ss = m & (S_ - 1);
                    const float pos = (float)tokpos[ss];
                    float sn, cs;
                    sincosf(pos * fr, &sn, &cs);
                    float e  = acc[mt][nt][2 * rr];
                    float od = acc[mt][nt][2 * rr + 1];
                    float v0 = e * cs - od * sn;
                    float v1 = e * sn + od * cs;
                    if (DEST == 1) { v0 *= SC_Q; v1 *= SC_Q; }
                    size_t ib = (((size_t)(bb * H_ + h)) * S_ + ss) * DK_ + dk;
                    *(uint32_t*)(Dst + ib) = packh2(v0, v1);
                }
            }
        }
    }
}

// ---------------------------------------------------------------------------
// Flash attention, fp16 k16. CTA = 64q x 64kv, 4 warps, 4 CTA/SM (46KB smem).
// P stays in registers (C-fragment == next A-fragment). V pre-transposed.
// ---------------------------------------------------------------------------
#define AROWB 144                            // 64 halves padded to 144B
#define AQ_B (64*AROWB)                      // 9216 B (Q region)
#define AKV_B (2*64*AROWB)                   // 18432 B per stage (K+V)
#define ATT_SMEM (AQ_B + 2*AKV_B)            // 46080 -> 4 CTA/SM

__global__ __launch_bounds__(128)
void attn_f16()
{
    extern __shared__ __align__(16) char sm[];
    const int tid = threadIdx.x;
    const int lane = tid & 31, w = tid >> 5;
    const int qt = (int)(gridDim.x - 1 - blockIdx.x);  // long rows first
    const int h  = blockIdx.y, b = blockIdx.z;
    const int q0 = qt * 64;
    const size_t gqk = ((size_t)(b * H_ + h)) * S_ * DK_;
    const size_t gvt = ((size_t)(b * H_ + h)) * DK_ * S_;

    // Q tile: 64 rows x 8 chunks(16B)
#pragma unroll
    for (int i = 0; i < 4; i++) {
        int idx = tid + i * 128;
        int r = idx >> 3, ch = idx & 7;
        cp16(smem_u32(sm + r * AROWB + ch * 16),
             g_Q + gqk + (size_t)(q0 + r) * DK_ + ch * 8);
    }
    auto load_kv = [&](int st, int kt) {
        char* sK = sm + AQ_B + st * AKV_B;
        char* sV = sK + 64 * AROWB;
#pragma unroll
        for (int i = 0; i < 4; i++) {
            int idx = tid + i * 128;
            int r = idx >> 3, ch = idx & 7;
            cp16(smem_u32(sK + r * AROWB + ch * 16),
                 g_K + gqk + (size_t)(kt * 64 + r) * DK_ + ch * 8);
            cp16(smem_u32(sV + r * AROWB + ch * 16),
                 g_V + gvt + (size_t)r * S_ + kt * 64 + ch * 8);
        }
    };
    load_kv(0, 0); CP_COMMIT();
    if (qt >= 1) load_kv(1, 1);
    CP_COMMIT();

    CP_WAIT1();
    __syncthreads();

    // Q A-fragments (fixed across kv tiles): 4 k16 steps
    const uint32_t sbase = smem_u32(sm);
    const int ri = lane & 7, mi = lane >> 3;
    const uint32_t q_lm = (uint32_t)((w * 16 + (lane & 15)) * AROWB + ((lane >> 4) << 4));
    const uint32_t kb_lm = (uint32_t)((ri + 8 * (mi >> 1)) * AROWB + (mi & 1) * 16);
    uint32_t qf[4][4];
#pragma unroll
    for (int ks = 0; ks < 4; ks++)
        ldm4(qf[ks], sbase + q_lm + ks * 32);

    float o[8][4];
#pragma unroll
    for (int d = 0; d < 8; d++)
#pragma unroll
        for (int r = 0; r < 4; r++) o[d][r] = 0.f;
    float mi0 = -1e30f, mi1 = -1e30f, li0 = 0.f, li1 = 0.f;
    const int row_lo = w * 16 + (lane >> 2);
    const int colx   = 2 * (lane & 3);

    for (int kt = 0; kt <= qt; kt++) {
        if (kt) { CP_WAIT1(); __syncthreads(); }
        const uint32_t sK = sbase + AQ_B + (kt & 1) * AKV_B;
        const uint32_t sV = sK + 64 * AROWB;

        // ---- S = Q K^T ----
        float s[8][4];
#pragma unroll
        for (int nt = 0; nt < 8; nt++)
#pragma unroll
            for (int r = 0; r < 4; r++) s[nt][r] = 0.f;
#pragma unroll
        for (int ks = 0; ks < 4; ks++)
#pragma unroll
            for (int j = 0; j < 4; j++) {
                uint32_t kb[4];
                ldm4(kb, sK + kb_lm + j * 16 * AROWB + ks * 32);
                mma_f16(s[2 * j],     qf[ks], kb[0], kb[1]);
                mma_f16(s[2 * j + 1], qf[ks], kb[2], kb[3]);
            }

        if (kt == qt) {   // causal mask on diagonal tile
#pragma unroll
            for (int nt = 0; nt < 8; nt++) {
                const int c = nt * 8 + colx;
                if (c     > row_lo)     s[nt][0] = -1e30f;
                if (c + 1 > row_lo)     s[nt][1] = -1e30f;
                if (c     > row_lo + 8) s[nt][2] = -1e30f;
                if (c + 1 > row_lo + 8) s[nt][3] = -1e30f;
            }
        }

        // ---- online softmax (base-2; scale folded into Q) ----
        float r0 = -1e30f, r1 = -1e30f;
#pragma unroll
        for (int nt = 0; nt < 8; nt++) {
            r0 = fmaxf(r0, fmaxf(s[nt][0], s[nt][1]));
            r1 = fmaxf(r1, fmaxf(s[nt][2], s[nt][3]));
        }
        r0 = fmaxf(r0, __shfl_xor_sync(0xffffffffu, r0, 1));
        r0 = fmaxf(r0, __shfl_xor_sync(0xffffffffu, r0, 2));
        r1 = fmaxf(r1, __shfl_xor_sync(0xffffffffu, r1, 1));
        r1 = fmaxf(r1, __shfl_xor_sync(0xffffffffu, r1, 2));
        const float mn0 = fmaxf(mi0, r0), mn1 = fmaxf(mi1, r1);
        const float c0 = ex2f(mi0 - mn0), c1 = ex2f(mi1 - mn1);
        float sum0 = 0.f, sum1 = 0.f;
#pragma unroll
        for (int nt = 0; nt < 8; nt++) {
            s[nt][0] = ex2f(s[nt][0] - mn0);
            s[nt][1] = ex2f(s[nt][1] - mn0);
            s[nt][2] = ex2f(s[nt][2] - mn1);
            s[nt][3] = ex2f(s[nt][3] - mn1);
            sum0 += s[nt][0] + s[nt][1];
            sum1 += s[nt][2] + s[nt][3];
        }
        sum0 += __shfl_xor_sync(0xffffffffu, sum0, 1);
        sum0 += __shfl_xor_sync(0xffffffffu, sum0, 2);
        sum1 += __shfl_xor_sync(0xffffffffu, sum1, 1);
        sum1 += __shfl_xor_sync(0xffffffffu, sum1, 2);
        li0 = li0 * c0 + sum0; li1 = li1 * c1 + sum1;
        mi0 = mn0; mi1 = mn1;
#pragma unroll
        for (int d = 0; d < 8; d++) {
            o[d][0] *= c0; o[d][1] *= c0; o[d][2] *= c1; o[d][3] *= c1;
        }

        // ---- O += P V : P packed in registers (C-frag == A-frag layout) ----
#pragma unroll
        for (int ks = 0; ks < 4; ks++) {
            uint32_t pa[4];
            pa[0] = packh2(s[2 * ks][0],     s[2 * ks][1]);
            pa[1] = packh2(s[2 * ks][2],     s[2 * ks][3]);
            pa[2] = packh2(s[2 * ks + 1][0], s[2 * ks + 1][1]);
            pa[3] = packh2(s[2 * ks + 1][2], s[2 * ks + 1][3]);
#pragma unroll
            for (int j = 0; j < 4; j++) {
                uint32_t vb[4];
                ldm4(vb, sV + kb_lm + j * 16 * AROWB + ks * 32);
                mma_f16(o[2 * j],     pa, vb[0], vb[1]);
                mma_f16(o[2 * j + 1], pa, vb[2], vb[3]);
            }
        }

        __syncthreads();
        if (kt + 2 <= qt) load_kv(kt & 1, kt + 2);
        CP_COMMIT();
    }

    // ---- epilogue: normalize, write fp16 [B,S,H*DK] ----
    const float inv0 = 1.f / li0, inv1 = 1.f / li1;
    const int grow0 = q0 + row_lo;
#pragma unroll
    for (int d = 0; d < 8; d++) {
        const int cb = h * 64 + d * 8 + colx;
        *(uint32_t*)(g_AOh + ((size_t)b * S_ + grow0) * D_ + cb) =
            packh2(o[d][0] * inv0, o[d][1] * inv0);
        *(uint32_t*)(g_AOh + ((size_t)b * S_ + grow0 + 8) * D_ + cb) =
            packh2(o[d][2] * inv1, o[d][3] * inv1);
    }
}

// ---------------------------------------------------------------------------
// Host
// ---------------------------------------------------------------------------
extern "C" void kernel_launch(void* const* d_in, const int* in_sizes, int n_in,
                              void* d_out, int out_size)
{
    const float* x  = (const float*)d_in[0];
    const float* qw = (const float*)d_in[1];
    const float* kw = (const float*)d_in[2];
    const float* vw = (const float*)d_in[3];
    const float* ow = (const float*)d_in[4];
    const int*   tp = (const int*)d_in[6];
    float* out = (float*)d_out;

    void *xh, *wh, *aoh;
    cudaGetSymbolAddress(&xh,  g_Xh);
    cudaGetSymbolAddress(&wh,  g_Wh);
    cudaGetSymbolAddress(&aoh, g_AOh);
    __half* Xh  = (__half*)xh;
    __half* Wh  = (__half*)wh;
    __half* AOh = (__half*)aoh;

    conv_x<<<M_*D_/8/256, 256>>>(x, Xh);
    dim3 wgrid(D_*D_/8/256, 4);
    conv_w4<<<wgrid, 256>>>(qw, kw, vw, ow, Wh);

    cudaFuncSetAttribute(gemm_f16<0>, cudaFuncAttributeMaxDynamicSharedMemorySize, TSMEM);
    cudaFuncSetAttribute(gemm_f16<1>, cudaFuncAttributeMaxDynamicSharedMemorySize, TSMEM);
    cudaFuncSetAttribute(gemm_f16<2>, cudaFuncAttributeMaxDynamicSharedMemorySize, TSMEM);
    cudaFuncSetAttribute(gemm_f16<3>, cudaFuncAttributeMaxDynamicSharedMemorySize, TSMEM);
    cudaFuncSetAttribute(attn_f16, cudaFuncAttributeMaxDynamicSharedMemorySize, ATT_SMEM);

    dim3 ggrid(M_ / BM, D_ / BN);   // (32, 8)
    gemm_f16<1><<<ggrid, 256, TSMEM>>>(Xh, Wh,                   nullptr, tp);
    gemm_f16<2><<<ggrid, 256, TSMEM>>>(Xh, Wh + 1*(size_t)D_*D_, nullptr, tp);
    gemm_f16<3><<<ggrid, 256, TSMEM>>>(Xh, Wh + 2*(size_t)D_*D_, nullptr, tp);

    dim3 agrid(S_ / 64, H_, B_);    // (32, 16, 2)
    attn_f16<<<agrid, 128, ATT_SMEM>>>();

    gemm_f16<0><<<ggrid, 256, TSMEM>>>(AOh, Wh + 3*(size_t)D_*D_, out, tp);
}

// round 14
// speedup vs baseline: 2.2543x; 1.0001x over previous
#include <cuda_runtime.h>
#include <cuda_fp16.h>
#include <math.h>
#include <stdint.h>

#define B_  2
#define S_  2048
#define D_  1024
#define H_  16
#define DK_ 64
#define M_  (B_*S_)

// ---------------------------------------------------------------------------
// Scratch (__device__ globals; allocation-free contract)
// ---------------------------------------------------------------------------
__device__ __align__(16) __half g_Xh [M_*D_];            // X fp16
__device__ __align__(16) __half g_Wh [4*(size_t)D_*D_];  // weights fp16 [mat][n][k]
__device__ __align__(16) __half g_AOh[M_*D_];            // attn out fp16 [B,S,D]
__device__ __align__(16) __half g_Q[B_*H_*S_*DK_];       // [B,H,S,DK], *log2(e)/8
__device__ __align__(16) __half g_K[B_*H_*S_*DK_];       // [B,H,S,DK]
__device__ __align__(16) __half g_V[B_*H_*S_*DK_];       // [B,H,DK,S] (transposed)

// ---------------------------------------------------------------------------
// PTX wrappers
// ---------------------------------------------------------------------------
__device__ __forceinline__ uint32_t smem_u32(const void* p) {
    uint32_t a;
    asm("{ .reg .u64 t; cvta.to.shared.u64 t, %1; cvt.u32.u64 %0, t; }"
        : "=r"(a) : "l"(p));
    return a;
}
__device__ __forceinline__ void cp16(uint32_t dst, const void* src) {
    asm volatile("cp.async.cg.shared.global [%0], [%1], 16;"
                 :: "r"(dst), "l"(src));
}
#define CP_COMMIT() asm volatile("cp.async.commit_group;")
#define CP_WAIT1()  asm volatile("cp.async.wait_group 1;")

__device__ __forceinline__ void ldm4(uint32_t (&a)[4], uint32_t addr) {
    asm volatile("ldmatrix.sync.aligned.m8n8.x4.shared.b16 {%0,%1,%2,%3}, [%4];"
                 : "=r"(a[0]), "=r"(a[1]), "=r"(a[2]), "=r"(a[3]) : "r"(addr));
}
__device__ __forceinline__ void mma_f16(float (&d)[4], const uint32_t (&a)[4],
                                        uint32_t b0, uint32_t b1) {
    asm volatile(
        "mma.sync.aligned.m16n8k16.row.col.f32.f16.f16.f32 "
        "{%0,%1,%2,%3}, {%4,%5,%6,%7}, {%8,%9}, {%0,%1,%2,%3};"
        : "+f"(d[0]), "+f"(d[1]), "+f"(d[2]), "+f"(d[3])
        : "r"(a[0]), "r"(a[1]), "r"(a[2]), "r"(a[3]), "r"(b0), "r"(b1));
}
__device__ __forceinline__ float ex2f(float x) {
    float y; asm("ex2.approx.f32 %0, %1;" : "=f"(y) : "f"(x)); return y;
}
__device__ __forceinline__ uint32_t packh2(float a, float b) {
    uint32_t r;
    asm("cvt.rn.f16x2.f32 %0, %1, %2;" : "=r"(r) : "f"(b), "f"(a));
    return r;
}

#define SC_Q 0.18033688011112042f   // log2(e)/8, folded into Q at projection

// ---------------------------------------------------------------------------
// Prep: fp32 -> fp16 (rn).
// ---------------------------------------------------------------------------
__device__ __forceinline__ void conv8h(const float* src, __half* dst, size_t i) {
    float4 v = *(const float4*)(src + i);
    float4 w = *(const float4*)(src + i + 4);
    uint4 r;
    r.x = packh2(v.x, v.y);
    r.y = packh2(v.z, v.w);
    r.z = packh2(w.x, w.y);
    r.w = packh2(w.z, w.w);
    *(uint4*)(dst + i) = r;
}
__global__ __launch_bounds__(256)
void conv_x(const float* __restrict__ src, __half* __restrict__ dst)
{
    size_t i = ((size_t)blockIdx.x * blockDim.x + threadIdx.x) * 8;
    conv8h(src, dst, i);
}
__global__ __launch_bounds__(256)
void conv_w4(const float* __restrict__ w0, const float* __restrict__ w1,
             const float* __restrict__ w2, const float* __restrict__ w3,
             __half* __restrict__ dst)
{
    const float* srcs[4] = {w0, w1, w2, w3};
    const float* src = srcs[blockIdx.y];
    __half* d = dst + (size_t)blockIdx.y * D_ * D_;
    size_t i = ((size_t)blockIdx.x * blockDim.x + threadIdx.x) * 8;
    conv8h(src, d, i);
}

// ---------------------------------------------------------------------------
// fp16 GEMM: CTA 128x128, 16 warps of 32x32 (512 thr), BK=64, 3-stage, 2 CTA/SM.
// 32 warps/SM for latency hiding; acc = 32 regs/thread.
// DEST: 0 = Cout fp32 [M,D]; 1 = g_Q (+RoPE,*SC_Q); 2 = g_K (+RoPE);
//       3 = g_V transposed [B,H,DK,S]
// ---------------------------------------------------------------------------
#define BM 128
#define BN 128
#define BK 64
#define NIT (D_/BK)                      // 16
#define HROWB 144                        // 64 halves padded to 144 bytes
#define TSB_OFFB (BM*HROWB)              // 18432
#define TSTG ((BM+BN)*HROWB)             // 36864 bytes
#define NSTG 3
#define TSMEM (NSTG*TSTG)                // 110592 -> 2 CTA/SM
#define GTHR 512

template<int DEST>
__global__ __launch_bounds__(GTHR, 2)
void gemm_f16(const __half* __restrict__ A, const __half* __restrict__ W,
              float* __restrict__ Cout, const int* __restrict__ tokpos)
{
    extern __shared__ __align__(16) char smem[];
    const int tid  = threadIdx.x;
    const int lane = tid & 31, w = tid >> 5;   // 16 warps
    const int wm = (w & 3) * 32;
    const int wn = (w >> 2) * 32;
    const int m0 = blockIdx.x * BM;
    const int n0 = blockIdx.y * BN;

    auto load_stage = [&](int st, int it) {
        char* s = smem + st * TSTG;
        const int kk = it * BK;
#pragma unroll
        for (int i = 0; i < 2; i++) {           // A: 128 rows x 8 chunks(16B)
            int idx = tid + i * GTHR;
            int row = idx >> 3, ch = idx & 7;
            cp16(smem_u32(s + row * HROWB + ch * 16),
                 A + (size_t)(m0 + row) * D_ + kk + ch * 8);
        }
        char* sB = s + TSB_OFFB;
#pragma unroll
        for (int i = 0; i < 2; i++) {           // B: 128 rows x 8 chunks
            int idx = tid + i * GTHR;
            int row = idx >> 3, ch = idx & 7;
            cp16(smem_u32(sB + row * HROWB + ch * 16),
                 W + (size_t)(n0 + row) * D_ + kk + ch * 8);
        }
    };

    float acc[2][4][4];
#pragma unroll
    for (int mt = 0; mt < 2; mt++)
#pragma unroll
        for (int nt = 0; nt < 4; nt++)
#pragma unroll
            for (int r = 0; r < 4; r++) acc[mt][nt][r] = 0.f;

    load_stage(0, 0); CP_COMMIT();
    load_stage(1, 1); CP_COMMIT();

    // ldmatrix lane addresses (bytes within stage)
    const uint32_t sbase = smem_u32(smem);
    const int ri = lane & 7, mi = lane >> 3;
    // A x4: m0=r[0:8)k-lo, m1=r[8:16)k-lo, m2=r[0:8)k-hi, m3=r[8:16)k-hi
    const uint32_t a_lm = (uint32_t)((wm + (lane & 15)) * HROWB + ((lane >> 4) << 4));
    // B x4: m0=n[0:8)k-lo, m1=n[0:8)k-hi, m2=n[8:16)k-lo, m3=n[8:16)k-hi
    const uint32_t b_lm = (uint32_t)(TSB_OFFB + (wn + ri + 8 * (mi >> 1)) * HROWB
                                     + (mi & 1) * 16);

    for (int it = 0; it < NIT; it++) {
        CP_WAIT1();
        __syncthreads();
        if (it + 2 < NIT) load_stage((it + 2) % NSTG, it + 2);
        CP_COMMIT();

        const uint32_t st = sbase + (uint32_t)((it % NSTG) * TSTG);
#pragma unroll
        for (int ks = 0; ks < 4; ks++) {        // 4 k16 steps in BK=64
            uint32_t a0[4], a1[4];
            ldm4(a0, st + a_lm + ks * 32);
            ldm4(a1, st + a_lm + 16 * HROWB + ks * 32);
#pragma unroll
            for (int j = 0; j < 2; j++) {       // 2 B x4 loads = 32 cols
                uint32_t bb[4];
                ldm4(bb, st + b_lm + j * 16 * HROWB + ks * 32);
                mma_f16(acc[0][2 * j],     a0, bb[0], bb[1]);
                mma_f16(acc[1][2 * j],     a1, bb[0], bb[1]);
                mma_f16(acc[0][2 * j + 1], a0, bb[2], bb[3]);
                mma_f16(acc[1][2 * j + 1], a1, bb[2], bb[3]);
            }
        }
    }

#pragma unroll
    for (int mt = 0; mt < 2; mt++) {
        const int r0 = m0 + wm + mt * 16 + (lane >> 2);
#pragma unroll
        for (int nt = 0; nt < 4; nt++) {
            const int ncol = n0 + wn + nt * 8 + (lane & 3) * 2;   // even
            if (DEST == 0) {
                *(float2*)(Cout + (size_t)r0 * D_ + ncol) =
                    make_float2(acc[mt][nt][0], acc[mt][nt][1]);
                *(float2*)(Cout + (size_t)(r0 + 8) * D_ + ncol) =
                    make_float2(acc[mt][nt][2], acc[mt][nt][3]);
            } else if (DEST == 3) {
                const int h = ncol >> 6, dk = ncol & 63;
#pragma unroll
                for (int rr = 0; rr < 2; rr++) {
                    const int m = r0 + rr * 8;
                    const int bb = m >> 11, ss = m & (S_ - 1);
                    size_t base = ((size_t)(bb * H_ + h)) * DK_ * S_;
                    g_V[base + (size_t)dk * S_ + ss] =
                        __float2half_rn(acc[mt][nt][2 * rr]);
                    g_V[base + (size_t)(dk + 1) * S_ + ss] =
                        __float2half_rn(acc[mt][nt][2 * rr + 1]);
                }
            } else {
                __half* Dst = (DEST == 1) ? g_Q : g_K;
                const int h = ncol >> 6, dk = ncol & 63;   // even: RoPE pair
                const float fr = powf(10000.f, -(float)dk / 64.f);
#pragma unroll
                for (int rr = 0; rr < 2; rr++) {
                    const int m = r0 + rr * 8;
                    const int bb = m >> 11, ss = m & (S_ - 1);
                    const float pos = (float)tokpos[ss];
                    float sn, cs;
                    sincosf(pos * fr, &sn, &cs);
                    float e  = acc[mt][nt][2 * rr];
                    float od = acc[mt][nt][2 * rr + 1];
                    float v0 = e * cs - od * sn;
                    float v1 = e * sn + od * cs;
                    if (DEST == 1) { v0 *= SC_Q; v1 *= SC_Q; }
                    size_t ib = (((size_t)(bb * H_ + h)) * S_ + ss) * DK_ + dk;
                    *(uint32_t*)(Dst + ib) = packh2(v0, v1);
                }
            }
        }
    }
}

// ---------------------------------------------------------------------------
// Flash attention, fp16 k16 (R13 version, verified). CTA 64q x 64kv, 4 warps,
// 4 CTA/SM. P register-resident. V pre-transposed.
// ---------------------------------------------------------------------------
#define AROWB 144
#define AQ_B (64*AROWB)
#define AKV_B (2*64*AROWB)
#define ATT_SMEM (AQ_B + 2*AKV_B)            // 46080 -> 4 CTA/SM

__global__ __launch_bounds__(128)
void attn_f16()
{
    extern __shared__ __align__(16) char sm[];
    const int tid = threadIdx.x;
    const int lane = tid & 31, w = tid >> 5;
    const int qt = (int)(gridDim.x - 1 - blockIdx.x);
    const int h  = blockIdx.y, b = blockIdx.z;
    const int q0 = qt * 64;
    const size_t gqk = ((size_t)(b * H_ + h)) * S_ * DK_;
    const size_t gvt = ((size_t)(b * H_ + h)) * DK_ * S_;

#pragma unroll
    for (int i = 0; i < 4; i++) {
        int idx = tid + i * 128;
        int r = idx >> 3, ch = idx & 7;
        cp16(smem_u32(sm + r * AROWB + ch * 16),
             g_Q + gqk + (size_t)(q0 + r) * DK_ + ch * 8);
    }
    auto load_kv = [&](int st, int kt) {
        char* sK = sm + AQ_B + st * AKV_B;
        char* sV = sK + 64 * AROWB;
#pragma unroll
        for (int i = 0; i < 4; i++) {
            int idx = tid + i * 128;
            int r = idx >> 3, ch = idx & 7;
            cp16(smem_u32(sK + r * AROWB + ch * 16),
                 g_K + gqk + (size_t)(kt * 64 + r) * DK_ + ch * 8);
            cp16(smem_u32(sV + r * AROWB + ch * 16),
                 g_V + gvt + (size_t)r * S_ + kt * 64 + ch * 8);
        }
    };
    load_kv(0, 0); CP_COMMIT();
    if (qt >= 1) load_kv(1, 1);
    CP_COMMIT();

    CP_WAIT1();
    __syncthreads();

    const uint32_t sbase = smem_u32(sm);
    const int ri = lane & 7, mi = lane >> 3;
    const uint32_t q_lm = (uint32_t)((w * 16 + (lane & 15)) * AROWB + ((lane >> 4) << 4));
    const uint32_t kb_lm = (uint32_t)((ri + 8 * (mi >> 1)) * AROWB + (mi & 1) * 16);
    uint32_t qf[4][4];
#pragma unroll
    for (int ks = 0; ks < 4; ks++)
        ldm4(qf[ks], sbase + q_lm + ks * 32);

    float o[8][4];
#pragma unroll
    for (int d = 0; d < 8; d++)
#pragma unroll
        for (int r = 0; r < 4; r++) o[d][r] = 0.f;
    float mi0 = -1e30f, mi1 = -1e30f, li0 = 0.f, li1 = 0.f;
    const int row_lo = w * 16 + (lane >> 2);
    const int colx   = 2 * (lane & 3);

    for (int kt = 0; kt <= qt; kt++) {
        if (kt) { CP_WAIT1(); __syncthreads(); }
        const uint32_t sK = sbase + AQ_B + (kt & 1) * AKV_B;
        const uint32_t sV = sK + 64 * AROWB;

        float s[8][4];
#pragma unroll
        for (int nt = 0; nt < 8; nt++)
#pragma unroll
            for (int r = 0; r < 4; r++) s[nt][r] = 0.f;
#pragma unroll
        for (int ks = 0; ks < 4; ks++)
#pragma unroll
            for (int j = 0; j < 4; j++) {
                uint32_t kb[4];
                ldm4(kb, sK + kb_lm + j * 16 * AROWB + ks * 32);
                mma_f16(s[2 * j],     qf[ks], kb[0], kb[1]);
                mma_f16(s[2 * j + 1], qf[ks], kb[2], kb[3]);
            }

        if (kt == qt) {
#pragma unroll
            for (int nt = 0; nt < 8; nt++) {
                const int c = nt * 8 + colx;
                if (c     > row_lo)     s[nt][0] = -1e30f;
                if (c + 1 > row_lo)     s[nt][1] = -1e30f;
                if (c     > row_lo + 8) s[nt][2] = -1e30f;
                if (c + 1 > row_lo + 8) s[nt][3] = -1e30f;
            }
        }

        float r0 = -1e30f, r1 = -1e30f;
#pragma unroll
        for (int nt = 0; nt < 8; nt++) {
            r0 = fmaxf(r0, fmaxf(s[nt][0], s[nt][1]));
            r1 = fmaxf(r1, fmaxf(s[nt][2], s[nt][3]));
        }
        r0 = fmaxf(r0, __shfl_xor_sync(0xffffffffu, r0, 1));
        r0 = fmaxf(r0, __shfl_xor_sync(0xffffffffu, r0, 2));
        r1 = fmaxf(r1, __shfl_xor_sync(0xffffffffu, r1, 1));
        r1 = fmaxf(r1, __shfl_xor_sync(0xffffffffu, r1, 2));
        const float mn0 = fmaxf(mi0, r0), mn1 = fmaxf(mi1, r1);
        const float c0 = ex2f(mi0 - mn0), c1 = ex2f(mi1 - mn1);
        float sum0 = 0.f, sum1 = 0.f;
#pragma unroll
        for (int nt = 0; nt < 8; nt++) {
            s[nt][0] = ex2f(s[nt][0] - mn0);
            s[nt][1] = ex2f(s[nt][1] - mn0);
            s[nt][2] = ex2f(s[nt][2] - mn1);
            s[nt][3] = ex2f(s[nt][3] - mn1);
            sum0 += s[nt][0] + s[nt][1];
            sum1 += s[nt][2] + s[nt][3];
        }
        sum0 += __shfl_xor_sync(0xffffffffu, sum0, 1);
        sum0 += __shfl_xor_sync(0xffffffffu, sum0, 2);
        sum1 += __shfl_xor_sync(0xffffffffu, sum1, 1);
        sum1 += __shfl_xor_sync(0xffffffffu, sum1, 2);
        li0 = li0 * c0 + sum0; li1 = li1 * c1 + sum1;
        mi0 = mn0; mi1 = mn1;
#pragma unroll
        for (int d = 0; d < 8; d++) {
            o[d][0] *= c0; o[d][1] *= c0; o[d][2] *= c1; o[d][3] *= c1;
        }

#pragma unroll
        for (int ks = 0; ks < 4; ks++) {
            uint32_t pa[4];
            pa[0] = packh2(s[2 * ks][0],     s[2 * ks][1]);
            pa[1] = packh2(s[2 * ks][2],     s[2 * ks][3]);
            pa[2] = packh2(s[2 * ks + 1][0], s[2 * ks + 1][1]);
            pa[3] = packh2(s[2 * ks + 1][2], s[2 * ks + 1][3]);
#pragma unroll
            for (int j = 0; j < 4; j++) {
                uint32_t vb[4];
                ldm4(vb, sV + kb_lm + j * 16 * AROWB + ks * 32);
                mma_f16(o[2 * j],     pa, vb[0], vb[1]);
                mma_f16(o[2 * j + 1], pa, vb[2], vb[3]);
            }
        }

        __syncthreads();
        if (kt + 2 <= qt) load_kv(kt & 1, kt + 2);
        CP_COMMIT();
    }

    const float inv0 = 1.f / li0, inv1 = 1.f / li1;
    const int grow0 = q0 + row_lo;
#pragma unroll
    for (int d = 0; d < 8; d++) {
        const int cb = h * 64 + d * 8 + colx;
        *(uint32_t*)(g_AOh + ((size_t)b * S_ + grow0) * D_ + cb) =
            packh2(o[d][0] * inv0, o[d][1] * inv0);
        *(uint32_t*)(g_AOh + ((size_t)b * S_ + grow0 + 8) * D_ + cb) =
            packh2(o[d][2] * inv1, o[d][3] * inv1);
    }
}

// ---------------------------------------------------------------------------
// Host
// ---------------------------------------------------------------------------
extern "C" void kernel_launch(void* const* d_in, const int* in_sizes, int n_in,
                              void* d_out, int out_size)
{
    const float* x  = (const float*)d_in[0];
    const float* qw = (const float*)d_in[1];
    const float* kw = (const float*)d_in[2];
    const float* vw = (const float*)d_in[3];
    const float* ow = (const float*)d_in[4];
    const int*   tp = (const int*)d_in[6];
    float* out = (float*)d_out;

    void *xh, *wh, *aoh;
    cudaGetSymbolAddress(&xh,  g_Xh);
    cudaGetSymbolAddress(&wh,  g_Wh);
    cudaGetSymbolAddress(&aoh, g_AOh);
    __half* Xh  = (__half*)xh;
    __half* Wh  = (__half*)wh;
    __half* AOh = (__half*)aoh;

    conv_x<<<M_*D_/8/256, 256>>>(x, Xh);
    dim3 wgrid(D_*D_/8/256, 4);
    conv_w4<<<wgrid, 256>>>(qw, kw, vw, ow, Wh);

    cudaFuncSetAttribute(gemm_f16<0>, cudaFuncAttributeMaxDynamicSharedMemorySize, TSMEM);
    cudaFuncSetAttribute(gemm_f16<1>, cudaFuncAttributeMaxDynamicSharedMemorySize, TSMEM);
    cudaFuncSetAttribute(gemm_f16<2>, cudaFuncAttributeMaxDynamicSharedMemorySize, TSMEM);
    cudaFuncSetAttribute(gemm_f16<3>, cudaFuncAttributeMaxDynamicSharedMemorySize, TSMEM);
    cudaFuncSetAttribute(attn_f16, cudaFuncAttributeMaxDynamicSharedMemorySize, ATT_SMEM);

    dim3 ggrid(M_ / BM, D_ / BN);   // (32, 8)
    gemm_f16<1><<<ggrid, GTHR, TSMEM>>>(Xh, Wh,                   nullptr, tp);
    gemm_f16<2><<<ggrid, GTHR, TSMEM>>>(Xh, Wh + 1*(size_t)D_*D_, nullptr, tp);
    gemm_f16<3><<<ggrid, GTHR, TSMEM>>>(Xh, Wh + 2*(size_t)D_*D_, nullptr, tp);

    dim3 agrid(S_ / 64, H_, B_);    // (32, 16, 2)
    attn_f16<<<agrid, 128, ATT_SMEM>>>();

    gemm_f16<0><<<ggrid, GTHR, TSMEM>>>(AOh, Wh + 3*(size_t)D_*D_, out, tp);
}

// round 15
// speedup vs baseline: 2.3834x; 1.0573x over previous
#include <cuda_runtime.h>
#include <cuda_fp16.h>
#include <math.h>
#include <stdint.h>

#define B_  2
#define S_  2048
#define D_  1024
#define H_  16
#define DK_ 64
#define M_  (B_*S_)

// ---------------------------------------------------------------------------
// Scratch (__device__ globals; allocation-free contract)
// ---------------------------------------------------------------------------
__device__ __align__(16) __half g_Xh [M_*D_];            // X fp16
__device__ __align__(16) __half g_Wh [4*(size_t)D_*D_];  // weights fp16 [mat][n][k]
__device__ __align__(16) __half g_AOh[M_*D_];            // attn out fp16 [B,S,D]
__device__ __align__(16) __half g_Q[B_*H_*S_*DK_];       // [B,H,S,DK], *log2(e)/8
__device__ __align__(16) __half g_K[B_*H_*S_*DK_];       // [B,H,S,DK]
__device__ __align__(16) __half g_V[B_*H_*S_*DK_];       // [B,H,DK,S] (transposed)

// ---------------------------------------------------------------------------
// PTX wrappers
// ---------------------------------------------------------------------------
__device__ __forceinline__ uint32_t smem_u32(const void* p) {
    uint32_t a;
    asm("{ .reg .u64 t; cvta.to.shared.u64 t, %1; cvt.u32.u64 %0, t; }"
        : "=r"(a) : "l"(p));
    return a;
}
__device__ __forceinline__ void cp16(uint32_t dst, const void* src) {
    asm volatile("cp.async.cg.shared.global [%0], [%1], 16;"
                 :: "r"(dst), "l"(src));
}
#define CP_COMMIT() asm volatile("cp.async.commit_group;")
#define CP_WAIT1()  asm volatile("cp.async.wait_group 1;")

__device__ __forceinline__ void ldm4(uint32_t (&a)[4], uint32_t addr) {
    asm volatile("ldmatrix.sync.aligned.m8n8.x4.shared.b16 {%0,%1,%2,%3}, [%4];"
                 : "=r"(a[0]), "=r"(a[1]), "=r"(a[2]), "=r"(a[3]) : "r"(addr));
}
__device__ __forceinline__ void mma_f16(float (&d)[4], const uint32_t (&a)[4],
                                        uint32_t b0, uint32_t b1) {
    asm volatile(
        "mma.sync.aligned.m16n8k16.row.col.f32.f16.f16.f32 "
        "{%0,%1,%2,%3}, {%4,%5,%6,%7}, {%8,%9}, {%0,%1,%2,%3};"
        : "+f"(d[0]), "+f"(d[1]), "+f"(d[2]), "+f"(d[3])
        : "r"(a[0]), "r"(a[1]), "r"(a[2]), "r"(a[3]), "r"(b0), "r"(b1));
}
__device__ __forceinline__ float ex2f(float x) {
    float y; asm("ex2.approx.f32 %0, %1;" : "=f"(y) : "f"(x)); return y;
}
__device__ __forceinline__ uint32_t packh2(float a, float b) {
    uint32_t r;
    asm("cvt.rn.f16x2.f32 %0, %1, %2;" : "=r"(r) : "f"(b), "f"(a));
    return r;
}

#define SC_Q 0.18033688011112042f   // log2(e)/8, folded into Q at projection

// ---------------------------------------------------------------------------
// Prep (single launch): blocks [0,2048) convert X, [2048,4096) convert W.
// ---------------------------------------------------------------------------
__device__ __forceinline__ void conv8h(const float* src, __half* dst, size_t i) {
    float4 v = *(const float4*)(src + i);
    float4 w = *(const float4*)(src + i + 4);
    uint4 r;
    r.x = packh2(v.x, v.y);
    r.y = packh2(v.z, v.w);
    r.z = packh2(w.x, w.y);
    r.w = packh2(w.z, w.w);
    *(uint4*)(dst + i) = r;
}
__global__ __launch_bounds__(256)
void conv_all(const float* __restrict__ x,
              const float* __restrict__ w0, const float* __restrict__ w1,
              const float* __restrict__ w2, const float* __restrict__ w3,
              __half* __restrict__ Xh, __half* __restrict__ Wh)
{
    const int bx = blockIdx.x;
    if (bx < 2048) {
        size_t i = ((size_t)bx * 256 + threadIdx.x) * 8;
        conv8h(x, Xh, i);
    } else {
        size_t j = ((size_t)(bx - 2048) * 256 + threadIdx.x) * 8;  // W element idx
        const int m = (int)(j >> 20);                               // which matrix
        const float* srcs[4] = {w0, w1, w2, w3};
        conv8h(srcs[m], Wh + ((size_t)m << 20), j & 1048575u);
    }
}

// ---------------------------------------------------------------------------
// fp16 GEMM: CTA 128x128, 16 warps of 32x32 (512 thr), BK=64, 3-stage, 2 CTA/SM.
// DEST 0: Cout fp32 [M,D] (O-projection, N=1024 grid)
// DEST 1: fused QKV epilogue — N=3072 grid over contiguous q,k,v weights.
//         mat 0 -> g_Q (+RoPE,*SC_Q), mat 1 -> g_K (+RoPE),
//         mat 2 -> g_V transposed [B,H,DK,S].
// ---------------------------------------------------------------------------
#define BM 128
#define BN 128
#define BK 64
#define NIT (D_/BK)                      // 16
#define HROWB 144
#define TSB_OFFB (BM*HROWB)
#define TSTG ((BM+BN)*HROWB)             // 36864 bytes
#define NSTG 3
#define TSMEM (NSTG*TSTG)                // 110592 -> 2 CTA/SM
#define GTHR 512

template<int DEST>
__global__ __launch_bounds__(GTHR, 2)
void gemm_f16(const __half* __restrict__ A, const __half* __restrict__ W,
              float* __restrict__ Cout, const int* __restrict__ tokpos)
{
    extern __shared__ __align__(16) char smem[];
    const int tid  = threadIdx.x;
    const int lane = tid & 31, w = tid >> 5;   // 16 warps
    const int wm = (w & 3) * 32;
    const int wn = (w >> 2) * 32;
    const int m0 = blockIdx.x * BM;
    const int n0 = blockIdx.y * BN;

    auto load_stage = [&](int st, int it) {
        char* s = smem + st * TSTG;
        const int kk = it * BK;
#pragma unroll
        for (int i = 0; i < 2; i++) {           // A: 128 rows x 8 chunks(16B)
            int idx = tid + i * GTHR;
            int row = idx >> 3, ch = idx & 7;
            cp16(smem_u32(s + row * HROWB + ch * 16),
                 A + (size_t)(m0 + row) * D_ + kk + ch * 8);
        }
        char* sB = s + TSB_OFFB;
#pragma unroll
        for (int i = 0; i < 2; i++) {           // B: 128 rows x 8 chunks
            int idx = tid + i * GTHR;
            int row = idx >> 3, ch = idx & 7;
            cp16(smem_u32(sB + row * HROWB + ch * 16),
                 W + (size_t)(n0 + row) * D_ + kk + ch * 8);
        }
    };

    float acc[2][4][4];
#pragma unroll
    for (int mt = 0; mt < 2; mt++)
#pragma unroll
        for (int nt = 0; nt < 4; nt++)
#pragma unroll
            for (int r = 0; r < 4; r++) acc[mt][nt][r] = 0.f;

    load_stage(0, 0); CP_COMMIT();
    load_stage(1, 1); CP_COMMIT();

    const uint32_t sbase = smem_u32(smem);
    const int ri = lane & 7, mi = lane >> 3;
    const uint32_t a_lm = (uint32_t)((wm + (lane & 15)) * HROWB + ((lane >> 4) << 4));
    const uint32_t b_lm = (uint32_t)(TSB_OFFB + (wn + ri + 8 * (mi >> 1)) * HROWB
                                     + (mi & 1) * 16);

    for (int it = 0; it < NIT; it++) {
        CP_WAIT1();
        __syncthreads();
        if (it + 2 < NIT) load_stage((it + 2) % NSTG, it + 2);
        CP_COMMIT();

        const uint32_t st = sbase + (uint32_t)((it % NSTG) * TSTG);
#pragma unroll
        for (int ks = 0; ks < 4; ks++) {
            uint32_t a0[4], a1[4];
            ldm4(a0, st + a_lm + ks * 32);
            ldm4(a1, st + a_lm + 16 * HROWB + ks * 32);
#pragma unroll
            for (int j = 0; j < 2; j++) {
                uint32_t bb[4];
                ldm4(bb, st + b_lm + j * 16 * HROWB + ks * 32);
                mma_f16(acc[0][2 * j],     a0, bb[0], bb[1]);
                mma_f16(acc[1][2 * j],     a1, bb[0], bb[1]);
                mma_f16(acc[0][2 * j + 1], a0, bb[2], bb[3]);
                mma_f16(acc[1][2 * j + 1], a1, bb[2], bb[3]);
            }
        }
    }

#pragma unroll
    for (int mt = 0; mt < 2; mt++) {
        const int r0 = m0 + wm + mt * 16 + (lane >> 2);
#pragma unroll
        for (int nt = 0; nt < 4; nt++) {
            const int ncol = n0 + wn + nt * 8 + (lane & 3) * 2;   // even
            if (DEST == 0) {
                *(float2*)(Cout + (size_t)r0 * D_ + ncol) =
                    make_float2(acc[mt][nt][0], acc[mt][nt][1]);
                *(float2*)(Cout + (size_t)(r0 + 8) * D_ + ncol) =
                    make_float2(acc[mt][nt][2], acc[mt][nt][3]);
            } else {
                const int mat = ncol >> 10;          // 0=Q, 1=K, 2=V
                const int c   = ncol & 1023;
                const int h = c >> 6, dk = c & 63;
                if (mat == 2) {
#pragma unroll
                    for (int rr = 0; rr < 2; rr++) {
                        const int m = r0 + rr * 8;
                        const int bb = m >> 11, ss = m & (S_ - 1);
                        size_t base = ((size_t)(bb * H_ + h)) * DK_ * S_;
                        g_V[base + (size_t)dk * S_ + ss] =
                            __float2half_rn(acc[mt][nt][2 * rr]);
                        g_V[base + (size_t)(dk + 1) * S_ + ss] =
                            __float2half_rn(acc[mt][nt][2 * rr + 1]);
                    }
                } else {
                    __half* Dst = (mat == 0) ? g_Q : g_K;
                    const float fr = powf(10000.f, -(float)dk / 64.f);
#pragma unroll
                    for (int rr = 0; rr < 2; rr++) {
                        const int m = r0 + rr * 8;
                        const int bb = m >> 11, ss = m & (S_ - 1);
                        const float pos = (float)tokpos[ss];
                        float sn, cs;
                        sincosf(pos * fr, &sn, &cs);
                        float e  = acc[mt][nt][2 * rr];
                        float od = acc[mt][nt][2 * rr + 1];
                        float v0 = e * cs - od * sn;
                        float v1 = e * sn + od * cs;
                        if (mat == 0) { v0 *= SC_Q; v1 *= SC_Q; }
                        size_t ib = (((size_t)(bb * H_ + h)) * S_ + ss) * DK_ + dk;
                        *(uint32_t*)(Dst + ib) = packh2(v0, v1);
                    }
                }
            }
        }
    }
}

// ---------------------------------------------------------------------------
// Flash attention, fp16 k16 (R13/R14 version, verified). CTA 64q x 64kv,
// 4 warps, 4 CTA/SM. P register-resident. V pre-transposed.
// ---------------------------------------------------------------------------
#define AROWB 144
#define AQ_B (64*AROWB)
#define AKV_B (2*64*AROWB)
#define ATT_SMEM (AQ_B + 2*AKV_B)            // 46080 -> 4 CTA/SM

__global__ __launch_bounds__(128)
void attn_f16()
{
    extern __shared__ __align__(16) char sm[];
    const int tid = threadIdx.x;
    const int lane = tid & 31, w = tid >> 5;
    const int qt = (int)(gridDim.x - 1 - blockIdx.x);
    const int h  = blockIdx.y, b = blockIdx.z;
    const int q0 = qt * 64;
    const size_t gqk = ((size_t)(b * H_ + h)) * S_ * DK_;
    const size_t gvt = ((size_t)(b * H_ + h)) * DK_ * S_;

#pragma unroll
    for (int i = 0; i < 4; i++) {
        int idx = tid + i * 128;
        int r = idx >> 3, ch = idx & 7;
        cp16(smem_u32(sm + r * AROWB + ch * 16),
             g_Q + gqk + (size_t)(q0 + r) * DK_ + ch * 8);
    }
    auto load_kv = [&](int st, int kt) {
        char* sK = sm + AQ_B + st * AKV_B;
        char* sV = sK + 64 * AROWB;
#pragma unroll
        for (int i = 0; i < 4; i++) {
            int idx = tid + i * 128;
            int r = idx >> 3, ch = idx & 7;
            cp16(smem_u32(sK + r * AROWB + ch * 16),
                 g_K + gqk + (size_t)(kt * 64 + r) * DK_ + ch * 8);
            cp16(smem_u32(sV + r * AROWB + ch * 16),
                 g_V + gvt + (size_t)r * S_ + kt * 64 + ch * 8);
        }
    };
    load_kv(0, 0); CP_COMMIT();
    if (qt >= 1) load_kv(1, 1);
    CP_COMMIT();

    CP_WAIT1();
    __syncthreads();

    const uint32_t sbase = smem_u32(sm);
    const int ri = lane & 7, mi = lane >> 3;
    const uint32_t q_lm = (uint32_t)((w * 16 + (lane & 15)) * AROWB + ((lane >> 4) << 4));
    const uint32_t kb_lm = (uint32_t)((ri + 8 * (mi >> 1)) * AROWB + (mi & 1) * 16);
    uint32_t qf[4][4];
#pragma unroll
    for (int ks = 0; ks < 4; ks++)
        ldm4(qf[ks], sbase + q_lm + ks * 32);

    float o[8][4];
#pragma unroll
    for (int d = 0; d < 8; d++)
#pragma unroll
        for (int r = 0; r < 4; r++) o[d][r] = 0.f;
    float mi0 = -1e30f, mi1 = -1e30f, li0 = 0.f, li1 = 0.f;
    const int row_lo = w * 16 + (lane >> 2);
    const int colx   = 2 * (lane & 3);

    for (int kt = 0; kt <= qt; kt++) {
        if (kt) { CP_WAIT1(); __syncthreads(); }
        const uint32_t sK = sbase + AQ_B + (kt & 1) * AKV_B;
        const uint32_t sV = sK + 64 * AROWB;

        float s[8][4];
#pragma unroll
        for (int nt = 0; nt < 8; nt++)
#pragma unroll
            for (int r = 0; r < 4; r++) s[nt][r] = 0.f;
#pragma unroll
        for (int ks = 0; ks < 4; ks++)
#pragma unroll
            for (int j = 0; j < 4; j++) {
                uint32_t kb[4];
                ldm4(kb, sK + kb_lm + j * 16 * AROWB + ks * 32);
                mma_f16(s[2 * j],     qf[ks], kb[0], kb[1]);
                mma_f16(s[2 * j + 1], qf[ks], kb[2], kb[3]);
            }

        if (kt == qt) {
#pragma unroll
            for (int nt = 0; nt < 8; nt++) {
                const int c = nt * 8 + colx;
                if (c     > row_lo)     s[nt][0] = -1e30f;
                if (c + 1 > row_lo)     s[nt][1] = -1e30f;
                if (c     > row_lo + 8) s[nt][2] = -1e30f;
                if (c + 1 > row_lo + 8) s[nt][3] = -1e30f;
            }
        }

        float r0 = -1e30f, r1 = -1e30f;
#pragma unroll
        for (int nt = 0; nt < 8; nt++) {
            r0 = fmaxf(r0, fmaxf(s[nt][0], s[nt][1]));
            r1 = fmaxf(r1, fmaxf(s[nt][2], s[nt][3]));
        }
        r0 = fmaxf(r0, __shfl_xor_sync(0xffffffffu, r0, 1));
        r0 = fmaxf(r0, __shfl_xor_sync(0xffffffffu, r0, 2));
        r1 = fmaxf(r1, __shfl_xor_sync(0xffffffffu, r1, 1));
        r1 = fmaxf(r1, __shfl_xor_sync(0xffffffffu, r1, 2));
        const float mn0 = fmaxf(mi0, r0), mn1 = fmaxf(mi1, r1);
        const float c0 = ex2f(mi0 - mn0), c1 = ex2f(mi1 - mn1);
        float sum0 = 0.f, sum1 = 0.f;
#pragma unroll
        for (int nt = 0; nt < 8; nt++) {
            s[nt][0] = ex2f(s[nt][0] - mn0);
            s[nt][1] = ex2f(s[nt][1] - mn0);
            s[nt][2] = ex2f(s[nt][2] - mn1);
            s[nt][3] = ex2f(s[nt][3] - mn1);
            sum0 += s[nt][0] + s[nt][1];
            sum1 += s[nt][2] + s[nt][3];
        }
        sum0 += __shfl_xor_sync(0xffffffffu, sum0, 1);
        sum0 += __shfl_xor_sync(0xffffffffu, sum0, 2);
        sum1 += __shfl_xor_sync(0xffffffffu, sum1, 1);
        sum1 += __shfl_xor_sync(0xffffffffu, sum1, 2);
        li0 = li0 * c0 + sum0; li1 = li1 * c1 + sum1;
        mi0 = mn0; mi1 = mn1;
#pragma unroll
        for (int d = 0; d < 8; d++) {
            o[d][0] *= c0; o[d][1] *= c0; o[d][2] *= c1; o[d][3] *= c1;
        }

#pragma unroll
        for (int ks = 0; ks < 4; ks++) {
            uint32_t pa[4];
            pa[0] = packh2(s[2 * ks][0],     s[2 * ks][1]);
            pa[1] = packh2(s[2 * ks][2],     s[2 * ks][3]);
            pa[2] = packh2(s[2 * ks + 1][0], s[2 * ks + 1][1]);
            pa[3] = packh2(s[2 * ks + 1][2], s[2 * ks + 1][3]);
#pragma unroll
            for (int j = 0; j < 4; j++) {
                uint32_t vb[4];
                ldm4(vb, sV + kb_lm + j * 16 * AROWB + ks * 32);
                mma_f16(o[2 * j],     pa, vb[0], vb[1]);
                mma_f16(o[2 * j + 1], pa, vb[2], vb[3]);
            }
        }

        __syncthreads();
        if (kt + 2 <= qt) load_kv(kt & 1, kt + 2);
        CP_COMMIT();
    }

    const float inv0 = 1.f / li0, inv1 = 1.f / li1;
    const int grow0 = q0 + row_lo;
#pragma unroll
    for (int d = 0; d < 8; d++) {
        const int cb = h * 64 + d * 8 + colx;
        *(uint32_t*)(g_AOh + ((size_t)b * S_ + grow0) * D_ + cb) =
            packh2(o[d][0] * inv0, o[d][1] * inv0);
        *(uint32_t*)(g_AOh + ((size_t)b * S_ + grow0 + 8) * D_ + cb) =
            packh2(o[d][2] * inv1, o[d][3] * inv1);
    }
}

// ---------------------------------------------------------------------------
// Host
// ---------------------------------------------------------------------------
extern "C" void kernel_launch(void* const* d_in, const int* in_sizes, int n_in,
                              void* d_out, int out_size)
{
    const float* x  = (const float*)d_in[0];
    const float* qw = (const float*)d_in[1];
    const float* kw = (const float*)d_in[2];
    const float* vw = (const float*)d_in[3];
    const float* ow = (const float*)d_in[4];
    const int*   tp = (const int*)d_in[6];
    float* out = (float*)d_out;

    void *xh, *wh, *aoh;
    cudaGetSymbolAddress(&xh,  g_Xh);
    cudaGetSymbolAddress(&wh,  g_Wh);
    cudaGetSymbolAddress(&aoh, g_AOh);
    __half* Xh  = (__half*)xh;
    __half* Wh  = (__half*)wh;
    __half* AOh = (__half*)aoh;

    conv_all<<<4096, 256>>>(x, qw, kw, vw, ow, Xh, Wh);

    cudaFuncSetAttribute(gemm_f16<0>, cudaFuncAttributeMaxDynamicSharedMemorySize, TSMEM);
    cudaFuncSetAttribute(gemm_f16<1>, cudaFuncAttributeMaxDynamicSharedMemorySize, TSMEM);
    cudaFuncSetAttribute(attn_f16, cudaFuncAttributeMaxDynamicSharedMemorySize, ATT_SMEM);

    // Fused QKV projection: one GEMM over N = 3072 (q,k,v weights contiguous)
    dim3 qkvgrid(M_ / BM, 3 * D_ / BN);   // (32, 24)
    gemm_f16<1><<<qkvgrid, GTHR, TSMEM>>>(Xh, Wh, nullptr, tp);

    dim3 agrid(S_ / 64, H_, B_);          // (32, 16, 2)
    attn_f16<<<agrid, 128, ATT_SMEM>>>();

    dim3 ogrid(M_ / BM, D_ / BN);         // (32, 8)
    gemm_f16<0><<<ogrid, GTHR, TSMEM>>>(AOh, Wh + 3*(size_t)D_*D_, out, tp);
}